// round 2
// baseline (speedup 1.0000x reference)
#include <cuda_runtime.h>

// ---------------- problem constants ----------------
#define NN 100000
#define RR 3
#define EE 1600000
#define HIDD 64
#define DF 129           // HID*2+1
#define KK 30            // sort-pool k
#define GG 64            // groups
#define NC1 16
#define NC2 32
#define KSZ 5
#define POOLL (KK/2)             // 15
#define TOUT (POOLL - KSZ + 1)   // 11
#define OUTL (NC2*TOUT)          // 352

#define NEGINF __int_as_float(0xff800000)

// ---------------- scratch (static device globals; no allocation allowed) ----
__device__ float g_dinv[NN];
__device__ int   g_cnt[NN];
__device__ int   g_off[NN + 1];
__device__ int   g_cur[NN];
__device__ int   g_eid[EE];
__device__ int   g_esrc[EE];
__device__ float g_ecoef[EE];
__device__ float g_hlin[NN * HIDD];
__device__ float g_h1[NN * HIDD];
__device__ float g_h2[NN * HIDD];
__device__ float g_h3lin[NN];
__device__ float g_feat[NN * DF];
__device__ int   g_gcnt[GG];
__device__ int   g_goff[GG + 1];
__device__ int   g_gcur[GG];
__device__ int   g_gids[NN];
__device__ float g_gscore[NN];
__device__ int   g_topk[GG * KK];
__device__ int   g_part[256];

// ---- XLA fast-tanh (llvm_ir::EmitFastTanh): rational 7/3 approx, clamp ±9,
// |x| < 0.0004 -> x. Evaluated with separate round-to-nearest mul/add (no FMA),
// matching XLA's emitted LLVM fmul/fadd sequence.
__device__ __forceinline__ float xla_tanh(float x) {
    float ax = fabsf(x);
    float cx = fminf(fmaxf(x, -9.0f), 9.0f);
    float x2 = __fmul_rn(cx, cx);
    float p = -2.76076847742355e-16f;
    p = __fadd_rn(__fmul_rn(p, x2), 2.00018790482477e-13f);
    p = __fadd_rn(__fmul_rn(p, x2), -8.60467152213735e-11f);
    p = __fadd_rn(__fmul_rn(p, x2), 5.12229709037114e-08f);
    p = __fadd_rn(__fmul_rn(p, x2), 1.48572235717979e-05f);
    p = __fadd_rn(__fmul_rn(p, x2), 6.37261928875436e-04f);
    p = __fadd_rn(__fmul_rn(p, x2), 4.89352455891786e-03f);
    float num = __fmul_rn(cx, p);
    float q = 1.19825839466702e-06f;
    q = __fadd_rn(__fmul_rn(q, x2), 1.18534705686654e-04f);
    q = __fadd_rn(__fmul_rn(q, x2), 2.26843463243900e-03f);
    q = __fadd_rn(__fmul_rn(q, x2), 4.89352518554385e-03f);
    float r = __fdiv_rn(num, q);
    return (ax < 0.0004f) ? x : r;
}

// ---------------- small utility kernels ----------------
__global__ void k_zero_out(float* out, int n) {
    int i = blockIdx.x * blockDim.x + threadIdx.x;
    if (i < n) out[i] = 0.f;
}

__global__ void k_init_cnt() {
    int i = blockIdx.x * blockDim.x + threadIdx.x;
    if (i < NN) g_cnt[i] = 0;
}

__global__ void k_count(const int* __restrict__ dst) {
    int e = blockIdx.x * blockDim.x + threadIdx.x;
    if (e < EE) atomicAdd(&g_cnt[dst[e]], 1);
}

// ---------------- exclusive scan over g_cnt -> g_off / g_cur ----------------
__global__ void k_scan1() {  // grid 98, block 1024
    __shared__ int s[1024];
    int t = threadIdx.x;
    int gid = blockIdx.x * 1024 + t;
    int v = (gid < NN) ? g_cnt[gid] : 0;
    s[t] = v; __syncthreads();
    for (int d = 1; d < 1024; d <<= 1) {
        int a = (t >= d) ? s[t - d] : 0;
        __syncthreads();
        s[t] += a;
        __syncthreads();
    }
    if (gid < NN) g_off[gid] = s[t];   // local inclusive (temp)
    if (t == 1023) g_part[blockIdx.x] = s[t];
}

__global__ void k_scan2(int nb) {  // single block 256
    __shared__ int s[256];
    int t = threadIdx.x;
    int v = (t < nb) ? g_part[t] : 0;
    s[t] = v; __syncthreads();
    for (int d = 1; d < 256; d <<= 1) {
        int a = (t >= d) ? s[t - d] : 0;
        __syncthreads();
        s[t] += a;
        __syncthreads();
    }
    if (t < nb) g_part[t] = s[t];  // inclusive over block sums
}

__global__ void k_scan3() {
    int i = blockIdx.x * blockDim.x + threadIdx.x;
    if (i < NN) {
        int b = i >> 10;
        int pref = (b > 0) ? g_part[b - 1] : 0;
        int excl = pref + g_off[i] - g_cnt[i];
        g_off[i] = excl;
        g_cur[i] = excl;
        if (i == 0) g_off[NN] = g_part[(NN + 1023) / 1024 - 1];
    }
}

__global__ void k_scatter_eid(const int* __restrict__ dst) {
    int e = blockIdx.x * blockDim.x + threadIdx.x;
    if (e < EE) {
        int pos = atomicAdd(&g_cur[dst[e]], 1);
        g_eid[pos] = e;
    }
}

// per-node insertion sort of edge ids -> stable ascending original edge order,
// replicating the accumulation order of XLA segment_sum.
__global__ void k_sortseg() {
    int n = blockIdx.x * blockDim.x + threadIdx.x;
    if (n >= NN) return;
    int s = g_off[n], e = g_off[n + 1];
    for (int i = s + 1; i < e; i++) {
        int key = g_eid[i];
        int j = i - 1;
        while (j >= s && g_eid[j] > key) { g_eid[j + 1] = g_eid[j]; j--; }
        g_eid[j + 1] = key;
    }
}

// deg = segment_sum(ew, dst) in ascending-edge order; dinv = 1/sqrt(deg+1)
__global__ void k_degdinv(const float* __restrict__ ew) {
    int n = blockIdx.x * blockDim.x + threadIdx.x;
    if (n >= NN) return;
    int s = g_off[n], e = g_off[n + 1];
    float deg = 0.f;
    for (int p = s; p < e; p++) deg = __fadd_rn(deg, ew[g_eid[p]]);
    g_dinv[n] = __fdiv_rn(1.0f, __fsqrt_rn(__fadd_rn(deg, 1.0f)));
}

// enorm = (dinv[src] * ew) * dinv[dst], left-associated rounding like jax
__global__ void k_coef(const int* __restrict__ src, const int* __restrict__ dst,
                       const float* __restrict__ ew, int total) {
    int p = blockIdx.x * blockDim.x + threadIdx.x;
    if (p < total) {
        int e = g_eid[p];
        int s = src[e];
        g_esrc[p]  = s;
        g_ecoef[p] = __fmul_rn(__fmul_rn(g_dinv[s], ew[e]), g_dinv[dst[e]]);
    }
}

// ---------------- SGEMM: [M x Kd] * [Kd x 64] -> g_hlin[M x 64] ----------------
// 128x64 tile, 128 threads, 8x8 register blocking. Single accumulator per
// output element, ascending-k FMA chain (matches Eigen gebp accumulation).
__global__ __launch_bounds__(128) void k_gemm(const float* __restrict__ Aext,
                                              const float* __restrict__ B,
                                              int M, int Kd, int asel) {
    const float* __restrict__ A = (asel == 0) ? Aext : g_h1;
    __shared__ float xT[32][132];
    __shared__ float ws[32][64];
    const int t  = threadIdx.x;
    const int tx = t & 7;       // 8 col groups (8 cols each)
    const int ty = t >> 3;      // 16 row groups (8 rows each)
    const int rowbase = blockIdx.x * 128;

    float acc[8][8];
#pragma unroll
    for (int i = 0; i < 8; i++)
#pragma unroll
        for (int j = 0; j < 8; j++) acc[i][j] = 0.f;

    for (int k0 = 0; k0 < Kd; k0 += 32) {
        for (int i = t; i < 128 * 32; i += 128) {
            int row = i >> 5, kk = i & 31;
            int gr = rowbase + row;
            xT[kk][row] = (gr < M) ? A[(size_t)gr * Kd + k0 + kk] : 0.f;
        }
        for (int i = t; i < 32 * 64; i += 128) {
            int kk = i >> 6, col = i & 63;
            ws[kk][col] = B[(size_t)(k0 + kk) * 64 + col];
        }
        __syncthreads();
#pragma unroll
        for (int kk = 0; kk < 32; kk++) {
            float4 a0 = *(const float4*)&xT[kk][ty * 8];
            float4 a1 = *(const float4*)&xT[kk][ty * 8 + 4];
            float4 b0 = *(const float4*)&ws[kk][tx * 8];
            float4 b1 = *(const float4*)&ws[kk][tx * 8 + 4];
            float a[8] = {a0.x, a0.y, a0.z, a0.w, a1.x, a1.y, a1.z, a1.w};
            float b[8] = {b0.x, b0.y, b0.z, b0.w, b1.x, b1.y, b1.z, b1.w};
#pragma unroll
            for (int i = 0; i < 8; i++)
#pragma unroll
                for (int j = 0; j < 8; j++) acc[i][j] = fmaf(a[i], b[j], acc[i][j]);
        }
        __syncthreads();
    }
#pragma unroll
    for (int i = 0; i < 8; i++) {
        int gr = rowbase + ty * 8 + i;
        if (gr < M) {
            float4 v0 = {acc[i][0], acc[i][1], acc[i][2], acc[i][3]};
            float4 v1 = {acc[i][4], acc[i][5], acc[i][6], acc[i][7]};
            *(float4*)&g_hlin[(size_t)gr * 64 + tx * 8]     = v0;
            *(float4*)&g_hlin[(size_t)gr * 64 + tx * 8 + 4] = v1;
        }
    }
}

// ---------------- aggregation (warp per node, 64-dim) ------------------------
// acc = sum_e round(enorm_e * h[src_e,d])  (ascending edge order, rn adds)
// then + round(snorm * h[n,d]), then + b[d], then xla_tanh.  Matches
// segment_sum -> + snorm*h -> + b -> tanh rounding sequence of the reference.
__global__ void k_agg64(const float* __restrict__ bias, int outsel, int featcol) {
    int gt   = blockIdx.x * blockDim.x + threadIdx.x;
    int n    = gt >> 5;
    int lane = gt & 31;
    if (n >= NN) return;
    float* __restrict__ hout = (outsel == 1) ? g_h1 : g_h2;

    int d0 = lane, d1 = lane + 32;
    float acc0 = 0.f, acc1 = 0.f;
    int e0 = g_off[n], e1 = g_off[n + 1];
    for (int e = e0; e < e1; e++) {
        float c = g_ecoef[e];
        int   s = g_esrc[e];
        acc0 = __fadd_rn(acc0, __fmul_rn(c, g_hlin[(size_t)s * 64 + d0]));
        acc1 = __fadd_rn(acc1, __fmul_rn(c, g_hlin[(size_t)s * 64 + d1]));
    }
    float dv = g_dinv[n];
    float sn = __fmul_rn(dv, dv);
    acc0 = __fadd_rn(acc0, __fmul_rn(sn, g_hlin[(size_t)n * 64 + d0]));
    acc1 = __fadd_rn(acc1, __fmul_rn(sn, g_hlin[(size_t)n * 64 + d1]));
    acc0 = __fadd_rn(acc0, bias[d0]);
    acc1 = __fadd_rn(acc1, bias[d1]);
    float v0 = xla_tanh(acc0);
    float v1 = xla_tanh(acc1);
    hout[(size_t)n * 64 + d0] = v0;
    hout[(size_t)n * 64 + d1] = v1;
    g_feat[(size_t)n * DF + featcol + d0] = v0;
    g_feat[(size_t)n * DF + featcol + d1] = v1;
}

// ---------------- layer 3: h2 @ W2 (64 -> 1), double accumulation ------------
__global__ void k_gemv3(const float* __restrict__ W2r) {
    int n = blockIdx.x * blockDim.x + threadIdx.x;
    if (n >= NN) return;
    const float* h = &g_h2[(size_t)n * 64];
    double acc = 0.0;
#pragma unroll
    for (int j = 0; j < 64; j++) acc += (double)h[j] * (double)W2r[j];
    g_h3lin[n] = (float)acc;
}

// scalar aggregation for the score channel (ascending edge order, rn ops)
__global__ void k_agg1(const float* __restrict__ b2r) {
    int n = blockIdx.x * blockDim.x + threadIdx.x;
    if (n >= NN) return;
    int e0 = g_off[n], e1 = g_off[n + 1];
    float acc = 0.f;
    for (int e = e0; e < e1; e++)
        acc = __fadd_rn(acc, __fmul_rn(g_ecoef[e], g_h3lin[g_esrc[e]]));
    float dv = g_dinv[n];
    float sn = __fmul_rn(dv, dv);
    acc = __fadd_rn(acc, __fmul_rn(sn, g_h3lin[n]));
    acc = __fadd_rn(acc, b2r[0]);
    g_feat[(size_t)n * DF + 128] = xla_tanh(acc);
}

// ---------------- group bucketing (relation-invariant) ----------------
__global__ void k_ginit() {
    int i = threadIdx.x;
    if (i < GG) g_gcnt[i] = 0;
}
__global__ void k_gcount(const int* __restrict__ grp) {
    int n = blockIdx.x * blockDim.x + threadIdx.x;
    if (n < NN) atomicAdd(&g_gcnt[grp[n]], 1);
}
__global__ void k_gscan() {  // 1 block, GG threads
    __shared__ int s[GG];
    int t = threadIdx.x;
    s[t] = g_gcnt[t]; __syncthreads();
    for (int d = 1; d < GG; d <<= 1) {
        int a = (t >= d) ? s[t - d] : 0;
        __syncthreads();
        s[t] += a;
        __syncthreads();
    }
    int excl = s[t] - g_gcnt[t];
    g_goff[t] = excl;
    g_gcur[t] = excl;
    if (t == GG - 1) g_goff[GG] = s[t];
}
__global__ void k_gscatter(const int* __restrict__ grp) {
    int n = blockIdx.x * blockDim.x + threadIdx.x;
    if (n < NN) {
        int pos = atomicAdd(&g_gcur[grp[n]], 1);
        g_gids[pos] = n;
    }
}

__global__ void k_gscore() {
    int i = blockIdx.x * blockDim.x + threadIdx.x;
    if (i < NN) g_gscore[i] = g_feat[(size_t)g_gids[i] * DF + 128];
}

// ---------------- per-group top-K (iterative argmax, ties -> lower node id) ----
__global__ void k_topk() {
    int g = blockIdx.x;
    int t = threadIdx.x;  // 256
    int base = g_goff[g];
    int cnt  = g_goff[g + 1] - base;
    __shared__ float ss[256];
    __shared__ int   si[256];
    __shared__ int   sp[256];
    for (int it = 0; it < KK; it++) {
        float bs = NEGINF;
        int bi = 0x7fffffff, bp = -1;
        for (int i = t; i < cnt; i += 256) {
            float sc = g_gscore[base + i];
            int   id = g_gids[base + i];
            if (sc > bs || (sc == bs && id < bi)) { bs = sc; bi = id; bp = base + i; }
        }
        ss[t] = bs; si[t] = bi; sp[t] = bp;
        __syncthreads();
        for (int d = 128; d > 0; d >>= 1) {
            if (t < d) {
                if (ss[t + d] > ss[t] || (ss[t + d] == ss[t] && si[t + d] < si[t])) {
                    ss[t] = ss[t + d]; si[t] = si[t + d]; sp[t] = sp[t + d];
                }
            }
            __syncthreads();
        }
        if (t == 0) {
            g_topk[g * KK + it] = si[0];
            if (sp[0] >= 0) g_gscore[sp[0]] = NEGINF;
        }
        __syncthreads();
    }
}

// ---------------- conv head (per group block), accumulates into out ----------
__global__ void k_conv(const float* __restrict__ w1, const float* __restrict__ b1,
                       const float* __restrict__ w2, const float* __restrict__ b2,
                       float* __restrict__ out) {
    int g = blockIdx.x, t = threadIdx.x;  // 256
    __shared__ float sf[KK * DF];         // 3870
    __shared__ float sw1[NC1 * DF];       // 2064
    __shared__ float sy[NC1 * KK];        // 480
    __shared__ float sp2[NC1 * POOLL];    // 240
    __shared__ float sw2[NC2 * NC1 * KSZ];// 2560

    for (int i = t; i < KK * DF; i += 256) {
        int row = i / DF, col = i - row * DF;
        sf[i] = g_feat[(size_t)g_topk[g * KK + row] * DF + col];
    }
    for (int i = t; i < NC1 * DF; i += 256) sw1[i] = w1[i];
    for (int i = t; i < NC2 * NC1 * KSZ; i += 256) sw2[i] = w2[i];
    __syncthreads();

    for (int o = t; o < NC1 * KK; o += 256) {
        int c = o / KK, tt = o - c * KK;
        float acc = b1[c];
#pragma unroll 4
        for (int j = 0; j < DF; j++) acc = fmaf(sw1[c * DF + j], sf[tt * DF + j], acc);
        sy[c * KK + tt] = fmaxf(acc, 0.f);
    }
    __syncthreads();

    for (int o = t; o < NC1 * POOLL; o += 256) {
        int c = o / POOLL, p = o - c * POOLL;
        sp2[c * POOLL + p] = fmaxf(sy[c * KK + 2 * p], sy[c * KK + 2 * p + 1]);
    }
    __syncthreads();

    for (int o2 = t; o2 < NC2 * TOUT; o2 += 256) {
        int o = o2 / TOUT, tt = o2 - o * TOUT;
        float acc = b2[o];
#pragma unroll
        for (int i = 0; i < NC1; i++)
#pragma unroll
            for (int k = 0; k < KSZ; k++)
                acc = fmaf(sw2[(o * NC1 + i) * KSZ + k], sp2[i * POOLL + tt + k], acc);
        out[g * OUTL + o * TOUT + tt] += fmaxf(acc, 0.f);
    }
}

// ---------------- launch ----------------
extern "C" void kernel_launch(void* const* d_in, const int* in_sizes, int n_in,
                              void* d_out, int out_size) {
    const float* x   = (const float*)d_in[0];
    const int*   ei  = (const int*)d_in[1];
    const float* ew  = (const float*)d_in[2];
    const int*   grp = (const int*)d_in[3];
    const float* W0  = (const float*)d_in[4];
    const float* b0  = (const float*)d_in[5];
    const float* W1  = (const float*)d_in[6];
    const float* b1  = (const float*)d_in[7];
    const float* W2  = (const float*)d_in[8];
    const float* b2  = (const float*)d_in[9];
    const float* c1w = (const float*)d_in[10];
    const float* c1b = (const float*)d_in[11];
    const float* c2w = (const float*)d_in[12];
    const float* c2b = (const float*)d_in[13];
    float* out = (float*)d_out;

    const int TB = 256;
    const int NB_N = (NN + TB - 1) / TB;
    const int NB_E = (EE + TB - 1) / TB;
    const int NB_W = (NN * 32 + TB - 1) / TB;  // warp-per-node grids
    const int SCAN_NB = (NN + 1023) / 1024;

    k_zero_out<<<(GG * OUTL + TB - 1) / TB, TB>>>(out, GG * OUTL);
    k_ginit<<<1, GG>>>();
    k_gcount<<<NB_N, TB>>>(grp);
    k_gscan<<<1, GG>>>();
    k_gscatter<<<NB_N, TB>>>(grp);

    for (int r = 0; r < RR; r++) {
        const int*   src = ei + (size_t)r * 2 * EE;
        const int*   dst = src + EE;
        const float* ewr = ew + (size_t)r * EE;

        // stable dst-CSR build (shared by all 3 layers of this relation)
        k_init_cnt<<<NB_N, TB>>>();
        k_count<<<NB_E, TB>>>(dst);
        k_scan1<<<SCAN_NB, 1024>>>();
        k_scan2<<<1, 256>>>(SCAN_NB);
        k_scan3<<<NB_N, TB>>>();
        k_scatter_eid<<<NB_E, TB>>>(dst);
        k_sortseg<<<NB_N, TB>>>();
        k_degdinv<<<NB_N, TB>>>(ewr);
        k_coef<<<NB_E, TB>>>(src, dst, ewr, EE);

        // layer 1: x @ W0[r] -> agg -> h1 / feat[:,0:64]
        k_gemm<<<(NN + 127) / 128, 128>>>(x, W0 + (size_t)r * 128 * 64, NN, 128, 0);
        k_agg64<<<NB_W, TB>>>(b0 + (size_t)r * 64, 1, 0);

        // layer 2: h1 @ W1[r] -> agg -> h2 / feat[:,64:128]
        k_gemm<<<(NN + 127) / 128, 128>>>(nullptr, W1 + (size_t)r * 64 * 64, NN, 64, 1);
        k_agg64<<<NB_W, TB>>>(b1 + (size_t)r * 64, 2, 64);

        // layer 3: h2 @ W2 (64->1) -> agg -> feat[:,128]
        k_gemv3<<<NB_N, TB>>>(W2 + (size_t)r * 64);
        k_agg1<<<NB_N, TB>>>(b2 + (size_t)r * 1);

        // sort-pool + conv head
        k_gscore<<<NB_N, TB>>>();
        k_topk<<<GG, 256>>>();
        k_conv<<<GG, 256>>>(c1w, c1b, c2w, c2b, out);
    }
}

// round 3
// speedup vs baseline: 1.2980x; 1.2980x over previous
#include <cuda_runtime.h>

// ---------------- problem constants ----------------
#define NN 100000
#define RR 3
#define EE 1600000
#define NT3 (RR * NN)            // 300000 flat nodes
#define ET3 (RR * EE)            // 4800000 flat edges
#define HIDD 64
#define DF 129                   // HID*2+1
#define KK 30                    // sort-pool k
#define GG 64                    // groups
#define NC1 16
#define NC2 32
#define KSZ 5
#define POOLL (KK/2)             // 15
#define TOUT (POOLL - KSZ + 1)   // 11
#define OUTL (NC2*TOUT)          // 352

#define NEGINF __int_as_float(0xff800000)

// ---------------- scratch (static device globals; no allocation allowed) ----
__device__ float g_dinv[NT3];
__device__ int   g_cnt[NT3];
__device__ int   g_off[NT3 + 1];
__device__ int   g_cur[NT3];
__device__ int   g_eid[ET3];
__device__ int   g_esrc[ET3];
__device__ float g_ecoef[ET3];
__device__ float g_hlin[(size_t)NT3 * HIDD];
__device__ float g_h1[(size_t)NT3 * HIDD];
__device__ float g_h3lin[NT3];
__device__ float g_feat[(size_t)NT3 * DF];
__device__ int   g_gcnt[GG];
__device__ int   g_goff[GG + 1];
__device__ int   g_gcur[GG];
__device__ int   g_gids[NN];
__device__ float g_gscore[NT3];
__device__ int   g_topk[RR * GG * KK];
__device__ float g_cout[RR * GG * OUTL];
__device__ int   g_part[512];

// ---- XLA fast-tanh (llvm_ir::EmitFastTanh): rational 7/3 approx, clamp ±9,
// |x| < 0.0004 -> x. Separate rn mul/add (no FMA contraction).
__device__ __forceinline__ float xla_tanh(float x) {
    float ax = fabsf(x);
    float cx = fminf(fmaxf(x, -9.0f), 9.0f);
    float x2 = __fmul_rn(cx, cx);
    float p = -2.76076847742355e-16f;
    p = __fadd_rn(__fmul_rn(p, x2), 2.00018790482477e-13f);
    p = __fadd_rn(__fmul_rn(p, x2), -8.60467152213735e-11f);
    p = __fadd_rn(__fmul_rn(p, x2), 5.12229709037114e-08f);
    p = __fadd_rn(__fmul_rn(p, x2), 1.48572235717979e-05f);
    p = __fadd_rn(__fmul_rn(p, x2), 6.37261928875436e-04f);
    p = __fadd_rn(__fmul_rn(p, x2), 4.89352455891786e-03f);
    float num = __fmul_rn(cx, p);
    float q = 1.19825839466702e-06f;
    q = __fadd_rn(__fmul_rn(q, x2), 1.18534705686654e-04f);
    q = __fadd_rn(__fmul_rn(q, x2), 2.26843463243900e-03f);
    q = __fadd_rn(__fmul_rn(q, x2), 4.89352518554385e-03f);
    float r = __fdiv_rn(num, q);
    return (ax < 0.0004f) ? x : r;
}

// ---------------- CSR build, batched over relations ----------------
__global__ void k_init_cnt() {
    int i = blockIdx.x * blockDim.x + threadIdx.x;
    if (i < NT3) g_cnt[i] = 0;
}

// edge_index layout: [R, 2, E]; dst of relation r at ei + r*2E + E
__global__ void k_count(const int* __restrict__ ei) {
    int e = blockIdx.x * blockDim.x + threadIdx.x;
    if (e < ET3) {
        int r  = e / EE;
        int le = e - r * EE;
        int d  = ei[(size_t)r * 2 * EE + EE + le];
        atomicAdd(&g_cnt[r * NN + d], 1);
    }
}

__global__ void k_scan1() {  // grid ceil(NT3/1024), block 1024
    __shared__ int s[1024];
    int t = threadIdx.x;
    int gid = blockIdx.x * 1024 + t;
    int v = (gid < NT3) ? g_cnt[gid] : 0;
    s[t] = v; __syncthreads();
    for (int d = 1; d < 1024; d <<= 1) {
        int a = (t >= d) ? s[t - d] : 0;
        __syncthreads();
        s[t] += a;
        __syncthreads();
    }
    if (gid < NT3) g_off[gid] = s[t];   // local inclusive (temp)
    if (t == 1023) g_part[blockIdx.x] = s[t];
}

__global__ void k_scan2(int nb) {  // single block 512
    __shared__ int s[512];
    int t = threadIdx.x;
    int v = (t < nb) ? g_part[t] : 0;
    s[t] = v; __syncthreads();
    for (int d = 1; d < 512; d <<= 1) {
        int a = (t >= d) ? s[t - d] : 0;
        __syncthreads();
        s[t] += a;
        __syncthreads();
    }
    if (t < nb) g_part[t] = s[t];
}

__global__ void k_scan3() {
    int i = blockIdx.x * blockDim.x + threadIdx.x;
    if (i < NT3) {
        int b = i >> 10;
        int pref = (b > 0) ? g_part[b - 1] : 0;
        int excl = pref + g_off[i] - g_cnt[i];
        g_off[i] = excl;
        g_cur[i] = excl;
        if (i == 0) g_off[NT3] = ET3;
    }
}

__global__ void k_scatter_eid(const int* __restrict__ ei) {
    int e = blockIdx.x * blockDim.x + threadIdx.x;
    if (e < ET3) {
        int r  = e / EE;
        int le = e - r * EE;
        int d  = ei[(size_t)r * 2 * EE + EE + le];
        int pos = atomicAdd(&g_cur[r * NN + d], 1);
        g_eid[pos] = le;
    }
}

// per-node insertion sort of local edge ids -> stable ascending original
// edge order, replicating XLA segment_sum accumulation order.
__global__ void k_sortseg() {
    int n = blockIdx.x * blockDim.x + threadIdx.x;
    if (n >= NT3) return;
    int s = g_off[n], e = g_off[n + 1];
    for (int i = s + 1; i < e; i++) {
        int key = g_eid[i];
        int j = i - 1;
        while (j >= s && g_eid[j] > key) { g_eid[j + 1] = g_eid[j]; j--; }
        g_eid[j + 1] = key;
    }
}

// deg = segment_sum(ew, dst) ascending-edge order; dinv = 1/sqrt(deg+1)
__global__ void k_degdinv(const float* __restrict__ ew) {
    int n = blockIdx.x * blockDim.x + threadIdx.x;
    if (n >= NT3) return;
    int r = n / NN;
    const float* ewr = ew + (size_t)r * EE;
    int s = g_off[n], e = g_off[n + 1];
    float deg = 0.f;
    for (int p = s; p < e; p++) deg = __fadd_rn(deg, ewr[g_eid[p]]);
    g_dinv[n] = __fdiv_rn(1.0f, __fsqrt_rn(__fadd_rn(deg, 1.0f)));
}

// enorm = (dinv[src] * ew) * dinv[dst], left-associated like the reference
__global__ void k_coef(const int* __restrict__ ei, const float* __restrict__ ew) {
    int p = blockIdx.x * blockDim.x + threadIdx.x;
    if (p < ET3) {
        int r  = p / EE;  // positions [r*EE,(r+1)*EE) belong to relation r
        int le = g_eid[p];
        const int* srcr = ei + (size_t)r * 2 * EE;
        const int* dstr = srcr + EE;
        int s = srcr[le];
        g_esrc[p]  = s;
        g_ecoef[p] = __fmul_rn(__fmul_rn(g_dinv[r * NN + s], ew[(size_t)r * EE + le]),
                               g_dinv[r * NN + dstr[le]]);
    }
}

// ---------------- SGEMM (batched over r): [M x Kd] * [Kd x 64] -> g_hlin ----
// 128x64 tile, 128 threads, 8x8 register blocking, packed fma.rn.f32x2.
// Per-element accumulation: single chain, ascending k — bitwise identical to
// scalar FFMA version (f32x2 = two independent IEEE fp32 FMAs).
__device__ __forceinline__ void fma2(unsigned long long& acc,
                                     unsigned long long a,
                                     unsigned long long b) {
    asm("fma.rn.f32x2 %0, %1, %2, %0;" : "+l"(acc) : "l"(a), "l"(b));
}

__global__ __launch_bounds__(128) void k_gemm(const float* __restrict__ Aext,
                                              const float* __restrict__ Ball,
                                              int Kd, int asel) {
    const int r = blockIdx.y;
    const float* __restrict__ A = (asel == 0) ? Aext : (g_h1 + (size_t)r * NN * HIDD);
    const float* __restrict__ B = Ball + (size_t)r * Kd * 64;
    float* __restrict__ C = g_hlin + (size_t)r * NN * HIDD;

    __shared__ float xT[32][132];
    __shared__ float ws[32][64];
    const int t  = threadIdx.x;
    const int tx = t & 7;       // 8 col groups (8 cols each)
    const int ty = t >> 3;      // 16 row groups (8 rows each)
    const int rowbase = blockIdx.x * 128;

    unsigned long long acc2[8][4];
#pragma unroll
    for (int i = 0; i < 8; i++)
#pragma unroll
        for (int j = 0; j < 4; j++) acc2[i][j] = 0ull;

    for (int k0 = 0; k0 < Kd; k0 += 32) {
        for (int i = t; i < 128 * 32; i += 128) {
            int row = i >> 5, kk = i & 31;
            int gr = rowbase + row;
            xT[kk][row] = (gr < NN) ? A[(size_t)gr * Kd + k0 + kk] : 0.f;
        }
        for (int i = t; i < 32 * 64; i += 128) {
            int kk = i >> 6, col = i & 63;
            ws[kk][col] = B[(size_t)(k0 + kk) * 64 + col];
        }
        __syncthreads();
#pragma unroll
        for (int kk = 0; kk < 32; kk++) {
            float4 a0 = *(const float4*)&xT[kk][ty * 8];
            float4 a1 = *(const float4*)&xT[kk][ty * 8 + 4];
            const ulonglong2* bp = (const ulonglong2*)&ws[kk][tx * 8];
            ulonglong2 b01 = bp[0];
            ulonglong2 b23 = bp[1];
            float a[8] = {a0.x, a0.y, a0.z, a0.w, a1.x, a1.y, a1.z, a1.w};
#pragma unroll
            for (int i = 0; i < 8; i++) {
                unsigned long long aa;
                asm("mov.b64 %0, {%1, %1};" : "=l"(aa) : "f"(a[i]));
                fma2(acc2[i][0], aa, b01.x);
                fma2(acc2[i][1], aa, b01.y);
                fma2(acc2[i][2], aa, b23.x);
                fma2(acc2[i][3], aa, b23.y);
            }
        }
        __syncthreads();
    }
#pragma unroll
    for (int i = 0; i < 8; i++) {
        int gr = rowbase + ty * 8 + i;
        if (gr < NN) {
            ulonglong2* o0 = (ulonglong2*)&C[(size_t)gr * 64 + tx * 8];
            o0[0] = make_ulonglong2(acc2[i][0], acc2[i][1]);
            o0[1] = make_ulonglong2(acc2[i][2], acc2[i][3]);
        }
    }
}

// ---------------- aggregation (warp per flat node, 64-dim) -------------------
// acc_d = sum_e rn(enorm_e * h[src_e,d]) ascending edge order, then
// + rn(snorm*h[n,d]) + b[d], then xla_tanh.  layer==2 additionally computes
// h3lin[n] = sum_d h2[n,d]*W2[d] (double butterfly).
__global__ void k_agg64(const float* __restrict__ biasAll,
                        const float* __restrict__ W2all, int layer) {
    int gt   = blockIdx.x * blockDim.x + threadIdx.x;
    int n    = gt >> 5;          // flat node id in [0, NT3)
    int lane = gt & 31;
    if (n >= NT3) return;
    int r = n / NN;
    const float* __restrict__ hl = g_hlin + (size_t)r * NN * HIDD;
    int ln = n - r * NN;         // local node
    const float* bias = biasAll + r * 64;

    int d0 = 2 * lane, d1 = 2 * lane + 1;
    float acc0 = 0.f, acc1 = 0.f;
    int e0 = g_off[n], e1 = g_off[n + 1];
    if (e0 < e1) {
        int   s = g_esrc[e0];
        float c = g_ecoef[e0];
        for (int e = e0; e + 1 < e1; e++) {
            int   s2 = g_esrc[e + 1];       // prefetch next edge header
            float c2 = g_ecoef[e + 1];
            float2 hv = *(const float2*)&hl[(size_t)s * 64 + d0];
            acc0 = __fadd_rn(acc0, __fmul_rn(c, hv.x));
            acc1 = __fadd_rn(acc1, __fmul_rn(c, hv.y));
            s = s2; c = c2;
        }
        float2 hv = *(const float2*)&hl[(size_t)s * 64 + d0];
        acc0 = __fadd_rn(acc0, __fmul_rn(c, hv.x));
        acc1 = __fadd_rn(acc1, __fmul_rn(c, hv.y));
    }
    float dv = g_dinv[n];
    float sn = __fmul_rn(dv, dv);
    float2 hs = *(const float2*)&hl[(size_t)ln * 64 + d0];
    acc0 = __fadd_rn(acc0, __fmul_rn(sn, hs.x));
    acc1 = __fadd_rn(acc1, __fmul_rn(sn, hs.y));
    acc0 = __fadd_rn(acc0, bias[d0]);
    acc1 = __fadd_rn(acc1, bias[d1]);
    float v0 = xla_tanh(acc0);
    float v1 = xla_tanh(acc1);

    size_t fb = (size_t)n * DF + (layer == 1 ? 0 : 64);
    g_feat[fb + d0] = v0;
    g_feat[fb + d1] = v1;
    if (layer == 1) {
        *(float2*)&g_h1[(size_t)n * 64 + d0] = make_float2(v0, v1);
    } else {
        const float* w2 = W2all + r * 64;
        double part = (double)v0 * (double)w2[d0] + (double)v1 * (double)w2[d1];
#pragma unroll
        for (int o = 16; o > 0; o >>= 1)
            part += __shfl_xor_sync(0xffffffffu, part, o);
        if (lane == 0) g_h3lin[n] = (float)part;
    }
}

// scalar aggregation for the score channel (ascending edge order, rn ops)
__global__ void k_agg1(const float* __restrict__ b2) {
    int n = blockIdx.x * blockDim.x + threadIdx.x;
    if (n >= NT3) return;
    int r = n / NN;
    int e0 = g_off[n], e1 = g_off[n + 1];
    float acc = 0.f;
    for (int e = e0; e < e1; e++)
        acc = __fadd_rn(acc, __fmul_rn(g_ecoef[e], g_h3lin[r * NN + g_esrc[e]]));
    float dv = g_dinv[n];
    float sn = __fmul_rn(dv, dv);
    acc = __fadd_rn(acc, __fmul_rn(sn, g_h3lin[n]));
    acc = __fadd_rn(acc, b2[r]);
    g_feat[(size_t)n * DF + 128] = xla_tanh(acc);
}

// ---------------- group bucketing (relation-invariant) ----------------
__global__ void k_ginit() {
    int i = threadIdx.x;
    if (i < GG) g_gcnt[i] = 0;
}
__global__ void k_gcount(const int* __restrict__ grp) {
    int n = blockIdx.x * blockDim.x + threadIdx.x;
    if (n < NN) atomicAdd(&g_gcnt[grp[n]], 1);
}
__global__ void k_gscan() {  // 1 block, GG threads
    __shared__ int s[GG];
    int t = threadIdx.x;
    s[t] = g_gcnt[t]; __syncthreads();
    for (int d = 1; d < GG; d <<= 1) {
        int a = (t >= d) ? s[t - d] : 0;
        __syncthreads();
        s[t] += a;
        __syncthreads();
    }
    int excl = s[t] - g_gcnt[t];
    g_goff[t] = excl;
    g_gcur[t] = excl;
    if (t == GG - 1) g_goff[GG] = s[t];
}
__global__ void k_gscatter(const int* __restrict__ grp) {
    int n = blockIdx.x * blockDim.x + threadIdx.x;
    if (n < NN) {
        int pos = atomicAdd(&g_gcur[grp[n]], 1);
        g_gids[pos] = n;
    }
}

__global__ void k_gscore() {
    int i = blockIdx.x * blockDim.x + threadIdx.x;
    if (i < NT3) {
        int r = i / NN, pos = i - r * NN;
        g_gscore[i] = g_feat[(size_t)(r * NN + g_gids[pos]) * DF + 128];
    }
}

// ---------------- per-(relation,group) top-K (iterative argmax) --------------
__global__ void k_topk() {
    int b = blockIdx.x;          // r*GG + g
    int r = b / GG, g = b - r * GG;
    int t = threadIdx.x;         // 256
    int base = g_goff[g];
    int cnt  = g_goff[g + 1] - base;
    const float* sc_base = g_gscore + (size_t)r * NN;
    __shared__ float ss[256];
    __shared__ int   si[256];
    __shared__ int   sp[256];
    for (int it = 0; it < KK; it++) {
        float bs = NEGINF;
        int bi = 0x7fffffff, bp = -1;
        for (int i = t; i < cnt; i += 256) {
            float sc = sc_base[base + i];
            int   id = g_gids[base + i];
            if (sc > bs || (sc == bs && id < bi)) { bs = sc; bi = id; bp = base + i; }
        }
        ss[t] = bs; si[t] = bi; sp[t] = bp;
        __syncthreads();
        for (int d = 128; d > 0; d >>= 1) {
            if (t < d) {
                if (ss[t + d] > ss[t] || (ss[t + d] == ss[t] && si[t + d] < si[t])) {
                    ss[t] = ss[t + d]; si[t] = si[t + d]; sp[t] = sp[t + d];
                }
            }
            __syncthreads();
        }
        if (t == 0) {
            g_topk[b * KK + it] = si[0];
            if (sp[0] >= 0) g_gscore[(size_t)r * NN + sp[0]] = NEGINF;
        }
        __syncthreads();
    }
}

// ---------------- conv head per (relation,group) -> g_cout -------------------
__global__ void k_conv(const float* __restrict__ w1, const float* __restrict__ b1,
                       const float* __restrict__ w2, const float* __restrict__ b2) {
    int b = blockIdx.x, t = threadIdx.x;  // 256
    int r = b / GG;
    __shared__ float sf[KK * DF];
    __shared__ float sw1[NC1 * DF];
    __shared__ float sy[NC1 * KK];
    __shared__ float sp2[NC1 * POOLL];
    __shared__ float sw2[NC2 * NC1 * KSZ];

    for (int i = t; i < KK * DF; i += 256) {
        int row = i / DF, col = i - row * DF;
        sf[i] = g_feat[(size_t)(r * NN + g_topk[b * KK + row]) * DF + col];
    }
    for (int i = t; i < NC1 * DF; i += 256) sw1[i] = w1[i];
    for (int i = t; i < NC2 * NC1 * KSZ; i += 256) sw2[i] = w2[i];
    __syncthreads();

    for (int o = t; o < NC1 * KK; o += 256) {
        int c = o / KK, tt = o - c * KK;
        float acc = b1[c];
#pragma unroll 4
        for (int j = 0; j < DF; j++) acc = fmaf(sw1[c * DF + j], sf[tt * DF + j], acc);
        sy[c * KK + tt] = fmaxf(acc, 0.f);
    }
    __syncthreads();

    for (int o = t; o < NC1 * POOLL; o += 256) {
        int c = o / POOLL, p = o - c * POOLL;
        sp2[c * POOLL + p] = fmaxf(sy[c * KK + 2 * p], sy[c * KK + 2 * p + 1]);
    }
    __syncthreads();

    for (int o2 = t; o2 < NC2 * TOUT; o2 += 256) {
        int o = o2 / TOUT, tt = o2 - o * TOUT;
        float acc = b2[o];
#pragma unroll
        for (int i = 0; i < NC1; i++)
#pragma unroll
            for (int k = 0; k < KSZ; k++)
                acc = fmaf(sw2[(o * NC1 + i) * KSZ + k], sp2[i * POOLL + tt + k], acc);
        g_cout[b * OUTL + o * TOUT + tt] = fmaxf(acc, 0.f);
    }
}

// sum over relations in fixed order ((y0 + y1) + y2), writes every output elem
__global__ void k_sumout(float* __restrict__ out) {
    int i = blockIdx.x * blockDim.x + threadIdx.x;
    if (i < GG * OUTL)
        out[i] = __fadd_rn(__fadd_rn(g_cout[i], g_cout[GG * OUTL + i]),
                           g_cout[2 * GG * OUTL + i]);
}

// ---------------- launch ----------------
extern "C" void kernel_launch(void* const* d_in, const int* in_sizes, int n_in,
                              void* d_out, int out_size) {
    const float* x   = (const float*)d_in[0];
    const int*   ei  = (const int*)d_in[1];
    const float* ew  = (const float*)d_in[2];
    const int*   grp = (const int*)d_in[3];
    const float* W0  = (const float*)d_in[4];
    const float* b0  = (const float*)d_in[5];
    const float* W1  = (const float*)d_in[6];
    const float* b1  = (const float*)d_in[7];
    const float* W2  = (const float*)d_in[8];
    const float* b2  = (const float*)d_in[9];
    const float* c1w = (const float*)d_in[10];
    const float* c1b = (const float*)d_in[11];
    const float* c2w = (const float*)d_in[12];
    const float* c2b = (const float*)d_in[13];
    float* out = (float*)d_out;

    const int TB = 256;
    const int NB_N  = (NN + TB - 1) / TB;
    const int NB_N3 = (NT3 + TB - 1) / TB;
    const int NB_E3 = (ET3 + TB - 1) / TB;
    const int NB_W3 = (NT3 * 32 + TB - 1) / TB;   // warp-per-node grid
    const int SCAN_NB = (NT3 + 1023) / 1024;      // 293

    // group bucketing (relation-invariant)
    k_ginit<<<1, GG>>>();
    k_gcount<<<NB_N, TB>>>(grp);
    k_gscan<<<1, GG>>>();
    k_gscatter<<<NB_N, TB>>>(grp);

    // stable dst-CSR for all relations at once
    k_init_cnt<<<NB_N3, TB>>>();
    k_count<<<NB_E3, TB>>>(ei);
    k_scan1<<<SCAN_NB, 1024>>>();
    k_scan2<<<1, 512>>>(SCAN_NB);
    k_scan3<<<NB_N3, TB>>>();
    k_scatter_eid<<<NB_E3, TB>>>(ei);
    k_sortseg<<<NB_N3, TB>>>();
    k_degdinv<<<NB_N3, TB>>>(ew);
    k_coef<<<NB_E3, TB>>>(ei, ew);

    dim3 gemm_grid((NN + 127) / 128, RR);

    // layer 1: x @ W0 -> agg -> h1 / feat[:,0:64]
    k_gemm<<<gemm_grid, 128>>>(x, W0, 128, 0);
    k_agg64<<<NB_W3, TB>>>(b0, nullptr, 1);

    // layer 2: h1 @ W1 -> agg -> feat[:,64:128], fused h3lin = h2 @ W2
    k_gemm<<<gemm_grid, 128>>>(nullptr, W1, 64, 1);
    k_agg64<<<NB_W3, TB>>>(b1, W2, 2);

    // layer 3 aggregation -> feat[:,128]
    k_agg1<<<NB_N3, TB>>>(b2);

    // sort-pool + conv head (batched over relations), then sum relations
    k_gscore<<<NB_N3, TB>>>();
    k_topk<<<RR * GG, 256>>>();
    k_conv<<<RR * GG, 256>>>(c1w, c1b, c2w, c2b);
    k_sumout<<<(GG * OUTL + TB - 1) / TB, TB>>>(out);
}

// round 4
// speedup vs baseline: 1.3030x; 1.0039x over previous
#include <cuda_runtime.h>

// ---------------- problem constants ----------------
#define NN 100000
#define RR 3
#define EE 1600000
#define NT3 (RR * NN)            // 300000 flat nodes
#define ET3 (RR * EE)            // 4800000 flat edges
#define HIDD 64
#define DF 129                   // HID*2+1
#define KK 30                    // sort-pool k
#define GG 64                    // groups
#define NC1 16
#define NC2 32
#define KSZ 5
#define POOLL (KK/2)             // 15
#define TOUT (POOLL - KSZ + 1)   // 11
#define OUTL (NC2*TOUT)          // 352
#define NREP 64                  // replicated group counters
#define GCAP 2048                // smem score capacity per group
#define DCAP 96                  // local-sort degree cap

#define NEGINF __int_as_float(0xff800000)

// ---------------- scratch (static device globals) ----------------
__device__ float g_dinv[NT3];
__device__ int   g_cnt[NT3];
__device__ int   g_off[NT3 + 1];
__device__ int   g_cur[NT3];
__device__ int   g_eid[ET3];
__device__ int   g_esrc[ET3];
__device__ float g_ecoef[ET3];
__device__ float g_hlin[(size_t)NT3 * HIDD];
__device__ float g_h1[(size_t)NT3 * HIDD];
__device__ float g_h3lin[NT3];
__device__ float g_feat[(size_t)NT3 * DF];
__device__ int   g_gcnt2[NREP][GG];
__device__ int   g_gcur2[NREP][GG];
__device__ int   g_goff[GG + 1];
__device__ int   g_gids[NN];
__device__ float g_cout[RR * GG * OUTL];
__device__ int   g_part[512];

// ---- XLA fast-tanh (llvm_ir::EmitFastTanh): rational 7/3, clamp ±9,
// |x| < 0.0004 -> x. Separate rn mul/add (no FMA contraction).
__device__ __forceinline__ float xla_tanh(float x) {
    float ax = fabsf(x);
    float cx = fminf(fmaxf(x, -9.0f), 9.0f);
    float x2 = __fmul_rn(cx, cx);
    float p = -2.76076847742355e-16f;
    p = __fadd_rn(__fmul_rn(p, x2), 2.00018790482477e-13f);
    p = __fadd_rn(__fmul_rn(p, x2), -8.60467152213735e-11f);
    p = __fadd_rn(__fmul_rn(p, x2), 5.12229709037114e-08f);
    p = __fadd_rn(__fmul_rn(p, x2), 1.48572235717979e-05f);
    p = __fadd_rn(__fmul_rn(p, x2), 6.37261928875436e-04f);
    p = __fadd_rn(__fmul_rn(p, x2), 4.89352455891786e-03f);
    float num = __fmul_rn(cx, p);
    float q = 1.19825839466702e-06f;
    q = __fadd_rn(__fmul_rn(q, x2), 1.18534705686654e-04f);
    q = __fadd_rn(__fmul_rn(q, x2), 2.26843463243900e-03f);
    q = __fadd_rn(__fmul_rn(q, x2), 4.89352518554385e-03f);
    float r = __fdiv_rn(num, q);
    return (ax < 0.0004f) ? x : r;
}

// ---------------- zero: g_cnt + replicated group counters ----------------
__global__ void k_zero() {
    int i = blockIdx.x * blockDim.x + threadIdx.x;
    if (i < NT3) g_cnt[i] = 0;
    if (i < NREP * GG) (&g_gcnt2[0][0])[i] = 0;
}

// ---------------- group bucketing with 64-way replicated counters -----------
__global__ void k_gcount(const int* __restrict__ grp) {
    int n = blockIdx.x * blockDim.x + threadIdx.x;
    if (n < NN) atomicAdd(&g_gcnt2[blockIdx.x & (NREP - 1)][grp[n]], 1);
}

__global__ void k_gscan() {  // 1 block, GG threads
    __shared__ int stot[GG];
    int g = threadIdx.x;
    int tot = 0;
    for (int rep = 0; rep < NREP; rep++) {
        int c = g_gcnt2[rep][g];
        g_gcnt2[rep][g] = tot;   // local base within group
        tot += c;
    }
    stot[g] = tot; __syncthreads();
    for (int d = 1; d < GG; d <<= 1) {
        int a = (g >= d) ? stot[g - d] : 0;
        __syncthreads();
        stot[g] += a;
        __syncthreads();
    }
    int excl = stot[g] - tot;
    g_goff[g] = excl;
    if (g == GG - 1) g_goff[GG] = stot[g];
    for (int rep = 0; rep < NREP; rep++)
        g_gcur2[rep][g] = excl + g_gcnt2[rep][g];
}

__global__ void k_gscatter(const int* __restrict__ grp) {
    int n = blockIdx.x * blockDim.x + threadIdx.x;
    if (n < NN) {
        int pos = atomicAdd(&g_gcur2[blockIdx.x & (NREP - 1)][grp[n]], 1);
        g_gids[pos] = n;
    }
}

// ---------------- CSR build, batched over relations ----------------
// edge_index layout: [R, 2, E]; dst of relation r at ei + r*2E + E
__global__ void k_count(const int* __restrict__ ei) {
    int e = blockIdx.x * blockDim.x + threadIdx.x;
    if (e < ET3) {
        int r  = e / EE;
        int le = e - r * EE;
        int d  = ei[(size_t)r * 2 * EE + EE + le];
        atomicAdd(&g_cnt[r * NN + d], 1);
    }
}

__global__ void k_scan1() {
    __shared__ int s[1024];
    int t = threadIdx.x;
    int gid = blockIdx.x * 1024 + t;
    int v = (gid < NT3) ? g_cnt[gid] : 0;
    s[t] = v; __syncthreads();
    for (int d = 1; d < 1024; d <<= 1) {
        int a = (t >= d) ? s[t - d] : 0;
        __syncthreads();
        s[t] += a;
        __syncthreads();
    }
    if (gid < NT3) g_off[gid] = s[t];
    if (t == 1023) g_part[blockIdx.x] = s[t];
}

__global__ void k_scan2(int nb) {
    __shared__ int s[512];
    int t = threadIdx.x;
    int v = (t < nb) ? g_part[t] : 0;
    s[t] = v; __syncthreads();
    for (int d = 1; d < 512; d <<= 1) {
        int a = (t >= d) ? s[t - d] : 0;
        __syncthreads();
        s[t] += a;
        __syncthreads();
    }
    if (t < nb) g_part[t] = s[t];
}

__global__ void k_scan3() {
    int i = blockIdx.x * blockDim.x + threadIdx.x;
    if (i < NT3) {
        int b = i >> 10;
        int pref = (b > 0) ? g_part[b - 1] : 0;
        int excl = pref + g_off[i] - g_cnt[i];
        g_off[i] = excl;
        g_cur[i] = excl;
        if (i == 0) g_off[NT3] = ET3;
    }
}

__global__ void k_scatter_eid(const int* __restrict__ ei) {
    int e = blockIdx.x * blockDim.x + threadIdx.x;
    if (e < ET3) {
        int r  = e / EE;
        int le = e - r * EE;
        int d  = ei[(size_t)r * 2 * EE + EE + le];
        int pos = atomicAdd(&g_cur[r * NN + d], 1);
        g_eid[pos] = le;
    }
}

// per-node sort of edge ids (ascending original order) in thread-local
// memory (L1-resident), then deg = segment_sum(ew) in that order.
__global__ void k_sortdeg(const float* __restrict__ ew) {
    int n = blockIdx.x * blockDim.x + threadIdx.x;
    if (n >= NT3) return;
    int r = n / NN;
    const float* ewr = ew + (size_t)r * EE;
    int s = g_off[n], e = g_off[n + 1];
    int d = e - s;
    float deg = 0.f;
    if (d <= DCAP) {
        int loc[DCAP];
        for (int i = 0; i < d; i++) loc[i] = g_eid[s + i];
        for (int i = 1; i < d; i++) {
            int key = loc[i];
            int j = i - 1;
            while (j >= 0 && loc[j] > key) { loc[j + 1] = loc[j]; j--; }
            loc[j + 1] = key;
        }
        for (int i = 0; i < d; i++) {
            g_eid[s + i] = loc[i];
            deg = __fadd_rn(deg, ewr[loc[i]]);
        }
    } else {  // rare fallback: global insertion sort
        for (int i = s + 1; i < e; i++) {
            int key = g_eid[i];
            int j = i - 1;
            while (j >= s && g_eid[j] > key) { g_eid[j + 1] = g_eid[j]; j--; }
            g_eid[j + 1] = key;
        }
        for (int p = s; p < e; p++) deg = __fadd_rn(deg, ewr[g_eid[p]]);
    }
    g_dinv[n] = __fdiv_rn(1.0f, __fsqrt_rn(__fadd_rn(deg, 1.0f)));
}

// enorm = (dinv[src] * ew) * dinv[dst], left-associated like the reference
__global__ void k_coef(const int* __restrict__ ei, const float* __restrict__ ew) {
    int p = blockIdx.x * blockDim.x + threadIdx.x;
    if (p < ET3) {
        int r  = p / EE;
        int le = g_eid[p];
        const int* srcr = ei + (size_t)r * 2 * EE;
        const int* dstr = srcr + EE;
        int s = srcr[le];
        g_esrc[p]  = s;
        g_ecoef[p] = __fmul_rn(__fmul_rn(g_dinv[r * NN + s], ew[(size_t)r * EE + le]),
                               g_dinv[r * NN + dstr[le]]);
    }
}

// ---------------- SGEMM (batched over r): [M x Kd] * [Kd x 64] -> g_hlin ----
// 128x64 tile, 128 threads, 8x8 register blocking, packed fma.rn.f32x2
// (two independent IEEE fp32 FMAs -> bitwise identical to scalar chain).
__device__ __forceinline__ void fma2(unsigned long long& acc,
                                     unsigned long long a,
                                     unsigned long long b) {
    asm("fma.rn.f32x2 %0, %1, %2, %0;" : "+l"(acc) : "l"(a), "l"(b));
}

__global__ __launch_bounds__(128) void k_gemm(const float* __restrict__ Aext,
                                              const float* __restrict__ Ball,
                                              int Kd, int asel) {
    const int r = blockIdx.y;
    const float* __restrict__ A = (asel == 0) ? Aext : (g_h1 + (size_t)r * NN * HIDD);
    const float* __restrict__ B = Ball + (size_t)r * Kd * 64;
    float* __restrict__ C = g_hlin + (size_t)r * NN * HIDD;

    __shared__ float xT[32][132];
    __shared__ float ws[32][64];
    const int t  = threadIdx.x;
    const int tx = t & 7;
    const int ty = t >> 3;
    const int rowbase = blockIdx.x * 128;

    unsigned long long acc2[8][4];
#pragma unroll
    for (int i = 0; i < 8; i++)
#pragma unroll
        for (int j = 0; j < 4; j++) acc2[i][j] = 0ull;

    for (int k0 = 0; k0 < Kd; k0 += 32) {
        for (int i = t; i < 128 * 32; i += 128) {
            int row = i >> 5, kk = i & 31;
            int gr = rowbase + row;
            xT[kk][row] = (gr < NN) ? A[(size_t)gr * Kd + k0 + kk] : 0.f;
        }
        for (int i = t; i < 32 * 64; i += 128) {
            int kk = i >> 6, col = i & 63;
            ws[kk][col] = B[(size_t)(k0 + kk) * 64 + col];
        }
        __syncthreads();
#pragma unroll
        for (int kk = 0; kk < 32; kk++) {
            float4 a0 = *(const float4*)&xT[kk][ty * 8];
            float4 a1 = *(const float4*)&xT[kk][ty * 8 + 4];
            const ulonglong2* bp = (const ulonglong2*)&ws[kk][tx * 8];
            ulonglong2 b01 = bp[0];
            ulonglong2 b23 = bp[1];
            float a[8] = {a0.x, a0.y, a0.z, a0.w, a1.x, a1.y, a1.z, a1.w};
#pragma unroll
            for (int i = 0; i < 8; i++) {
                unsigned long long aa;
                asm("mov.b64 %0, {%1, %1};" : "=l"(aa) : "f"(a[i]));
                fma2(acc2[i][0], aa, b01.x);
                fma2(acc2[i][1], aa, b01.y);
                fma2(acc2[i][2], aa, b23.x);
                fma2(acc2[i][3], aa, b23.y);
            }
        }
        __syncthreads();
    }
#pragma unroll
    for (int i = 0; i < 8; i++) {
        int gr = rowbase + ty * 8 + i;
        if (gr < NN) {
            ulonglong2* o0 = (ulonglong2*)&C[(size_t)gr * 64 + tx * 8];
            o0[0] = make_ulonglong2(acc2[i][0], acc2[i][1]);
            o0[1] = make_ulonglong2(acc2[i][2], acc2[i][3]);
        }
    }
}

// ---------------- aggregation (warp per flat node, 64-dim) -------------------
__global__ void k_agg64(const float* __restrict__ biasAll,
                        const float* __restrict__ W2all, int layer) {
    int gt   = blockIdx.x * blockDim.x + threadIdx.x;
    int n    = gt >> 5;
    int lane = gt & 31;
    if (n >= NT3) return;
    int r = n / NN;
    const float* __restrict__ hl = g_hlin + (size_t)r * NN * HIDD;
    int ln = n - r * NN;
    const float* bias = biasAll + r * 64;

    int d0 = 2 * lane, d1 = 2 * lane + 1;
    float acc0 = 0.f, acc1 = 0.f;
    int e0 = g_off[n], e1 = g_off[n + 1];
    if (e0 < e1) {
        int   s = g_esrc[e0];
        float c = g_ecoef[e0];
        for (int e = e0; e + 1 < e1; e++) {
            int   s2 = g_esrc[e + 1];
            float c2 = g_ecoef[e + 1];
            float2 hv = *(const float2*)&hl[(size_t)s * 64 + d0];
            acc0 = __fadd_rn(acc0, __fmul_rn(c, hv.x));
            acc1 = __fadd_rn(acc1, __fmul_rn(c, hv.y));
            s = s2; c = c2;
        }
        float2 hv = *(const float2*)&hl[(size_t)s * 64 + d0];
        acc0 = __fadd_rn(acc0, __fmul_rn(c, hv.x));
        acc1 = __fadd_rn(acc1, __fmul_rn(c, hv.y));
    }
    float dv = g_dinv[n];
    float sn = __fmul_rn(dv, dv);
    float2 hs = *(const float2*)&hl[(size_t)ln * 64 + d0];
    acc0 = __fadd_rn(acc0, __fmul_rn(sn, hs.x));
    acc1 = __fadd_rn(acc1, __fmul_rn(sn, hs.y));
    acc0 = __fadd_rn(acc0, bias[d0]);
    acc1 = __fadd_rn(acc1, bias[d1]);
    float v0 = xla_tanh(acc0);
    float v1 = xla_tanh(acc1);

    size_t fb = (size_t)n * DF + (layer == 1 ? 0 : 64);
    g_feat[fb + d0] = v0;
    g_feat[fb + d1] = v1;
    if (layer == 1) {
        *(float2*)&g_h1[(size_t)n * 64 + d0] = make_float2(v0, v1);
    } else {
        const float* w2 = W2all + r * 64;
        double part = (double)v0 * (double)w2[d0] + (double)v1 * (double)w2[d1];
#pragma unroll
        for (int o = 16; o > 0; o >>= 1)
            part += __shfl_xor_sync(0xffffffffu, part, o);
        if (lane == 0) g_h3lin[n] = (float)part;
    }
}

// scalar aggregation for the score channel
__global__ void k_agg1(const float* __restrict__ b2) {
    int n = blockIdx.x * blockDim.x + threadIdx.x;
    if (n >= NT3) return;
    int r = n / NN;
    int e0 = g_off[n], e1 = g_off[n + 1];
    float acc = 0.f;
    for (int e = e0; e < e1; e++)
        acc = __fadd_rn(acc, __fmul_rn(g_ecoef[e], g_h3lin[r * NN + g_esrc[e]]));
    float dv = g_dinv[n];
    float sn = __fmul_rn(dv, dv);
    acc = __fadd_rn(acc, __fmul_rn(sn, g_h3lin[n]));
    acc = __fadd_rn(acc, b2[r]);
    g_feat[(size_t)n * DF + 128] = xla_tanh(acc);
}

// ---------------- fused gscore + topk + conv per (relation,group) -----------
struct P1 { float sc[GCAP]; int id[GCAP]; };
struct P2 {
    float sf[KK * DF];
    float sw1[NC1 * DF];
    float sy[NC1 * KK];
    float sp2[NC1 * POOLL];
    float sw2[NC2 * NC1 * KSZ];
};
union PU { P1 p1; P2 p2; };

__global__ __launch_bounds__(256) void k_topk_conv(
        const float* __restrict__ w1, const float* __restrict__ b1,
        const float* __restrict__ w2, const float* __restrict__ b2) {
    int b = blockIdx.x;                  // r*GG + g
    int r = b / GG, g = b - r * GG;
    int t = threadIdx.x;                 // 256
    int base = g_goff[g];
    int cnt  = g_goff[g + 1] - base;

    __shared__ PU u;
    __shared__ float ss[256];
    __shared__ int   si[256];
    __shared__ int   sp[256];
    __shared__ int   stopk[KK];

    if (cnt <= GCAP) {
        for (int i = t; i < cnt; i += 256) {
            int id = g_gids[base + i];
            u.p1.id[i] = id;
            u.p1.sc[i] = g_feat[(size_t)(r * NN + id) * DF + 128];
        }
        __syncthreads();
        for (int it = 0; it < KK; it++) {
            float bs = NEGINF;
            int bi = 0x7fffffff, bp = -1;
            for (int i = t; i < cnt; i += 256) {
                float sc = u.p1.sc[i];
                int   id = u.p1.id[i];
                if (sc > bs || (sc == bs && id < bi)) { bs = sc; bi = id; bp = i; }
            }
            ss[t] = bs; si[t] = bi; sp[t] = bp;
            __syncthreads();
            for (int d = 128; d > 0; d >>= 1) {
                if (t < d) {
                    if (ss[t + d] > ss[t] || (ss[t + d] == ss[t] && si[t + d] < si[t])) {
                        ss[t] = ss[t + d]; si[t] = si[t + d]; sp[t] = sp[t + d];
                    }
                }
                __syncthreads();
            }
            if (t == 0) {
                stopk[it] = si[0];
                if (sp[0] >= 0) u.p1.sc[sp[0]] = NEGINF;
            }
            __syncthreads();
        }
    } else {  // fallback: re-read scores from global each pass, exclude chosen
        for (int it = 0; it < KK; it++) {
            float bs = NEGINF;
            int bi = 0x7fffffff, bp = -1;
            for (int i = t; i < cnt; i += 256) {
                int id = g_gids[base + i];
                bool taken = false;
                for (int j = 0; j < it; j++) taken |= (stopk[j] == id);
                if (taken) continue;
                float sc = g_feat[(size_t)(r * NN + id) * DF + 128];
                if (sc > bs || (sc == bs && id < bi)) { bs = sc; bi = id; bp = i; }
            }
            ss[t] = bs; si[t] = bi; sp[t] = bp;
            __syncthreads();
            for (int d = 128; d > 0; d >>= 1) {
                if (t < d) {
                    if (ss[t + d] > ss[t] || (ss[t + d] == ss[t] && si[t + d] < si[t])) {
                        ss[t] = ss[t + d]; si[t] = si[t + d]; sp[t] = sp[t + d];
                    }
                }
                __syncthreads();
            }
            if (t == 0) stopk[it] = si[0];
            __syncthreads();
        }
    }
    __syncthreads();

    // ---- conv head (smem reused via union) ----
    for (int i = t; i < KK * DF; i += 256) {
        int row = i / DF, col = i - row * DF;
        u.p2.sf[i] = g_feat[(size_t)(r * NN + stopk[row]) * DF + col];
    }
    for (int i = t; i < NC1 * DF; i += 256) u.p2.sw1[i] = w1[i];
    for (int i = t; i < NC2 * NC1 * KSZ; i += 256) u.p2.sw2[i] = w2[i];
    __syncthreads();

    for (int o = t; o < NC1 * KK; o += 256) {
        int c = o / KK, tt = o - c * KK;
        float acc = b1[c];
#pragma unroll 4
        for (int j = 0; j < DF; j++)
            acc = fmaf(u.p2.sw1[c * DF + j], u.p2.sf[tt * DF + j], acc);
        u.p2.sy[c * KK + tt] = fmaxf(acc, 0.f);
    }
    __syncthreads();

    for (int o = t; o < NC1 * POOLL; o += 256) {
        int c = o / POOLL, p = o - c * POOLL;
        u.p2.sp2[c * POOLL + p] = fmaxf(u.p2.sy[c * KK + 2 * p], u.p2.sy[c * KK + 2 * p + 1]);
    }
    __syncthreads();

    for (int o2 = t; o2 < NC2 * TOUT; o2 += 256) {
        int o = o2 / TOUT, tt = o2 - o * TOUT;
        float acc = b2[o];
#pragma unroll
        for (int i = 0; i < NC1; i++)
#pragma unroll
            for (int k = 0; k < KSZ; k++)
                acc = fmaf(u.p2.sw2[(o * NC1 + i) * KSZ + k],
                           u.p2.sp2[i * POOLL + tt + k], acc);
        g_cout[b * OUTL + o * TOUT + tt] = fmaxf(acc, 0.f);
    }
}

// sum over relations in fixed order ((y0 + y1) + y2)
__global__ void k_sumout(float* __restrict__ out) {
    int i = blockIdx.x * blockDim.x + threadIdx.x;
    if (i < GG * OUTL)
        out[i] = __fadd_rn(__fadd_rn(g_cout[i], g_cout[GG * OUTL + i]),
                           g_cout[2 * GG * OUTL + i]);
}

// ---------------- launch ----------------
extern "C" void kernel_launch(void* const* d_in, const int* in_sizes, int n_in,
                              void* d_out, int out_size) {
    const float* x   = (const float*)d_in[0];
    const int*   ei  = (const int*)d_in[1];
    const float* ew  = (const float*)d_in[2];
    const int*   grp = (const int*)d_in[3];
    const float* W0  = (const float*)d_in[4];
    const float* b0  = (const float*)d_in[5];
    const float* W1  = (const float*)d_in[6];
    const float* b1  = (const float*)d_in[7];
    const float* W2  = (const float*)d_in[8];
    const float* b2  = (const float*)d_in[9];
    const float* c1w = (const float*)d_in[10];
    const float* c1b = (const float*)d_in[11];
    const float* c2w = (const float*)d_in[12];
    const float* c2b = (const float*)d_in[13];
    float* out = (float*)d_out;

    const int TB = 256;
    const int NB_N  = (NN + TB - 1) / TB;
    const int NB_N3 = (NT3 + TB - 1) / TB;
    const int NB_E3 = (ET3 + TB - 1) / TB;
    const int NB_W3 = (NT3 * 32 + TB - 1) / TB;
    const int SCAN_NB = (NT3 + 1023) / 1024;

    k_zero<<<NB_N3, TB>>>();
    k_gcount<<<NB_N, TB>>>(grp);
    k_gscan<<<1, GG>>>();
    k_gscatter<<<NB_N, TB>>>(grp);

    k_count<<<NB_E3, TB>>>(ei);
    k_scan1<<<SCAN_NB, 1024>>>();
    k_scan2<<<1, 512>>>(SCAN_NB);
    k_scan3<<<NB_N3, TB>>>();
    k_scatter_eid<<<NB_E3, TB>>>(ei);
    k_sortdeg<<<NB_N3, TB>>>(ew);
    k_coef<<<NB_E3, TB>>>(ei, ew);

    dim3 gemm_grid((NN + 127) / 128, RR);

    k_gemm<<<gemm_grid, 128>>>(x, W0, 128, 0);
    k_agg64<<<NB_W3, TB>>>(b0, nullptr, 1);

    k_gemm<<<gemm_grid, 128>>>(nullptr, W1, 64, 1);
    k_agg64<<<NB_W3, TB>>>(b1, W2, 2);

    k_agg1<<<NB_N3, TB>>>(b2);

    k_topk_conv<<<RR * GG, 256>>>(c1w, c1b, c2w, c2b);
    k_sumout<<<(GG * OUTL + TB - 1) / TB, TB>>>(out);
}

// round 5
// speedup vs baseline: 1.3575x; 1.0418x over previous
#include <cuda_runtime.h>

// ---------------- problem constants ----------------
#define NN 100000
#define RR 3
#define EE 1600000
#define NT3 (RR * NN)            // 300000 flat nodes
#define ET3 (RR * EE)            // 4800000 flat edges
#define HIDD 64
#define DF 129                   // HID*2+1
#define KK 30                    // sort-pool k
#define GG 64                    // groups
#define NC1 16
#define NC2 32
#define KSZ 5
#define POOLL (KK/2)             // 15
#define TOUT (POOLL - KSZ + 1)   // 11
#define OUTL (NC2*TOUT)          // 352
#define NREP 64                  // replicated group counters
#define GCAP 2048                // smem score capacity per group
#define DCAP 96                  // local-sort degree cap

#define NEGINF __int_as_float(0xff800000)

// ---------------- scratch (static device globals) ----------------
__device__ float g_dinv[NT3];
__device__ int   g_cnt[NT3];
__device__ int   g_off[NT3 + 1];
__device__ int   g_cur[NT3];
__device__ int   g_eid[ET3];
__device__ float2 g_epair[ET3];        // {coef, bitcast(src)}
__device__ float g_hlin[(size_t)NT3 * HIDD];
__device__ float g_h1[(size_t)NT3 * HIDD];
__device__ float g_h3lin[NT3];
__device__ float g_feat[(size_t)NT3 * DF];
__device__ int   g_gcnt2[NREP][GG];
__device__ int   g_gcur2[NREP][GG];
__device__ int   g_goff[GG + 1];
__device__ int   g_gids[NN];
__device__ float g_cout[RR * GG * OUTL];
__device__ int   g_part[512];

// ---- XLA fast-tanh (llvm_ir::EmitFastTanh): rational 7/3, clamp ±9,
// |x| < 0.0004 -> x. Separate rn mul/add (no FMA contraction).
__device__ __forceinline__ float xla_tanh(float x) {
    float ax = fabsf(x);
    float cx = fminf(fmaxf(x, -9.0f), 9.0f);
    float x2 = __fmul_rn(cx, cx);
    float p = -2.76076847742355e-16f;
    p = __fadd_rn(__fmul_rn(p, x2), 2.00018790482477e-13f);
    p = __fadd_rn(__fmul_rn(p, x2), -8.60467152213735e-11f);
    p = __fadd_rn(__fmul_rn(p, x2), 5.12229709037114e-08f);
    p = __fadd_rn(__fmul_rn(p, x2), 1.48572235717979e-05f);
    p = __fadd_rn(__fmul_rn(p, x2), 6.37261928875436e-04f);
    p = __fadd_rn(__fmul_rn(p, x2), 4.89352455891786e-03f);
    float num = __fmul_rn(cx, p);
    float q = 1.19825839466702e-06f;
    q = __fadd_rn(__fmul_rn(q, x2), 1.18534705686654e-04f);
    q = __fadd_rn(__fmul_rn(q, x2), 2.26843463243900e-03f);
    q = __fadd_rn(__fmul_rn(q, x2), 4.89352518554385e-03f);
    float r = __fdiv_rn(num, q);
    return (ax < 0.0004f) ? x : r;
}

// ---------------- zero: g_cnt + replicated group counters ----------------
__global__ void k_zero() {
    int i = blockIdx.x * blockDim.x + threadIdx.x;
    if (i < NT3) g_cnt[i] = 0;
    if (i < NREP * GG) (&g_gcnt2[0][0])[i] = 0;
}

// ---------------- group bucketing with 64-way replicated counters -----------
__global__ void k_gcount(const int* __restrict__ grp) {
    int n = blockIdx.x * blockDim.x + threadIdx.x;
    if (n < NN) atomicAdd(&g_gcnt2[blockIdx.x & (NREP - 1)][grp[n]], 1);
}

__global__ void k_gscan() {  // 1 block, GG threads
    __shared__ int stot[GG];
    int g = threadIdx.x;
    int tot = 0;
    for (int rep = 0; rep < NREP; rep++) {
        int c = g_gcnt2[rep][g];
        g_gcnt2[rep][g] = tot;
        tot += c;
    }
    stot[g] = tot; __syncthreads();
    for (int d = 1; d < GG; d <<= 1) {
        int a = (g >= d) ? stot[g - d] : 0;
        __syncthreads();
        stot[g] += a;
        __syncthreads();
    }
    int excl = stot[g] - tot;
    g_goff[g] = excl;
    if (g == GG - 1) g_goff[GG] = stot[g];
    for (int rep = 0; rep < NREP; rep++)
        g_gcur2[rep][g] = excl + g_gcnt2[rep][g];
}

__global__ void k_gscatter(const int* __restrict__ grp) {
    int n = blockIdx.x * blockDim.x + threadIdx.x;
    if (n < NN) {
        int pos = atomicAdd(&g_gcur2[blockIdx.x & (NREP - 1)][grp[n]], 1);
        g_gids[pos] = n;
    }
}

// ---------------- CSR build, batched over relations ----------------
__global__ void k_count(const int* __restrict__ ei) {
    int e = blockIdx.x * blockDim.x + threadIdx.x;
    if (e < ET3) {
        int r  = e / EE;
        int le = e - r * EE;
        int d  = ei[(size_t)r * 2 * EE + EE + le];
        atomicAdd(&g_cnt[r * NN + d], 1);
    }
}

__global__ void k_scan1() {
    __shared__ int s[1024];
    int t = threadIdx.x;
    int gid = blockIdx.x * 1024 + t;
    int v = (gid < NT3) ? g_cnt[gid] : 0;
    s[t] = v; __syncthreads();
    for (int d = 1; d < 1024; d <<= 1) {
        int a = (t >= d) ? s[t - d] : 0;
        __syncthreads();
        s[t] += a;
        __syncthreads();
    }
    if (gid < NT3) g_off[gid] = s[t];
    if (t == 1023) g_part[blockIdx.x] = s[t];
}

__global__ void k_scan2(int nb) {
    __shared__ int s[512];
    int t = threadIdx.x;
    int v = (t < nb) ? g_part[t] : 0;
    s[t] = v; __syncthreads();
    for (int d = 1; d < 512; d <<= 1) {
        int a = (t >= d) ? s[t - d] : 0;
        __syncthreads();
        s[t] += a;
        __syncthreads();
    }
    if (t < nb) g_part[t] = s[t];
}

__global__ void k_scan3() {
    int i = blockIdx.x * blockDim.x + threadIdx.x;
    if (i < NT3) {
        int b = i >> 10;
        int pref = (b > 0) ? g_part[b - 1] : 0;
        int excl = pref + g_off[i] - g_cnt[i];
        g_off[i] = excl;
        g_cur[i] = excl;
        if (i == 0) g_off[NT3] = ET3;
    }
}

__global__ void k_scatter_eid(const int* __restrict__ ei) {
    int e = blockIdx.x * blockDim.x + threadIdx.x;
    if (e < ET3) {
        int r  = e / EE;
        int le = e - r * EE;
        int d  = ei[(size_t)r * 2 * EE + EE + le];
        int pos = atomicAdd(&g_cur[r * NN + d], 1);
        g_eid[pos] = le;
    }
}

// per-node sort of edge ids (ascending original order) in thread-local
// memory (L1-resident), then deg = segment_sum(ew) in that order.
__global__ void k_sortdeg(const float* __restrict__ ew) {
    int n = blockIdx.x * blockDim.x + threadIdx.x;
    if (n >= NT3) return;
    int r = n / NN;
    const float* ewr = ew + (size_t)r * EE;
    int s = g_off[n], e = g_off[n + 1];
    int d = e - s;
    float deg = 0.f;
    if (d <= DCAP) {
        int loc[DCAP];
        for (int i = 0; i < d; i++) loc[i] = g_eid[s + i];
        for (int i = 1; i < d; i++) {
            int key = loc[i];
            int j = i - 1;
            while (j >= 0 && loc[j] > key) { loc[j + 1] = loc[j]; j--; }
            loc[j + 1] = key;
        }
        for (int i = 0; i < d; i++) {
            g_eid[s + i] = loc[i];
            deg = __fadd_rn(deg, ewr[loc[i]]);
        }
    } else {
        for (int i = s + 1; i < e; i++) {
            int key = g_eid[i];
            int j = i - 1;
            while (j >= s && g_eid[j] > key) { g_eid[j + 1] = g_eid[j]; j--; }
            g_eid[j + 1] = key;
        }
        for (int p = s; p < e; p++) deg = __fadd_rn(deg, ewr[g_eid[p]]);
    }
    g_dinv[n] = __fdiv_rn(1.0f, __fsqrt_rn(__fadd_rn(deg, 1.0f)));
}

// packed edge header: {coef = (dinv[src]*ew)*dinv[dst], bitcast(src)}
__global__ void k_coef(const int* __restrict__ ei, const float* __restrict__ ew) {
    int p = blockIdx.x * blockDim.x + threadIdx.x;
    if (p < ET3) {
        int r  = p / EE;
        int le = g_eid[p];
        const int* srcr = ei + (size_t)r * 2 * EE;
        const int* dstr = srcr + EE;
        int s = srcr[le];
        float c = __fmul_rn(__fmul_rn(g_dinv[r * NN + s], ew[(size_t)r * EE + le]),
                            g_dinv[r * NN + dstr[le]]);
        g_epair[p] = make_float2(c, __int_as_float(s));
    }
}

// ---------------- SGEMM (batched over r): [M x Kd] * [Kd x 64] -> g_hlin ----
__device__ __forceinline__ void fma2(unsigned long long& acc,
                                     unsigned long long a,
                                     unsigned long long b) {
    asm("fma.rn.f32x2 %0, %1, %2, %0;" : "+l"(acc) : "l"(a), "l"(b));
}

__global__ __launch_bounds__(128) void k_gemm(const float* __restrict__ Aext,
                                              const float* __restrict__ Ball,
                                              int Kd, int asel) {
    const int r = blockIdx.y;
    const float* __restrict__ A = (asel == 0) ? Aext : (g_h1 + (size_t)r * NN * HIDD);
    const float* __restrict__ B = Ball + (size_t)r * Kd * 64;
    float* __restrict__ C = g_hlin + (size_t)r * NN * HIDD;

    __shared__ float xT[32][132];
    __shared__ float ws[32][64];
    const int t  = threadIdx.x;
    const int tx = t & 7;
    const int ty = t >> 3;
    const int rowbase = blockIdx.x * 128;

    unsigned long long acc2[8][4];
#pragma unroll
    for (int i = 0; i < 8; i++)
#pragma unroll
        for (int j = 0; j < 4; j++) acc2[i][j] = 0ull;

    for (int k0 = 0; k0 < Kd; k0 += 32) {
        for (int i = t; i < 128 * 32; i += 128) {
            int row = i >> 5, kk = i & 31;
            int gr = rowbase + row;
            xT[kk][row] = (gr < NN) ? A[(size_t)gr * Kd + k0 + kk] : 0.f;
        }
        for (int i = t; i < 32 * 64; i += 128) {
            int kk = i >> 6, col = i & 63;
            ws[kk][col] = B[(size_t)(k0 + kk) * 64 + col];
        }
        __syncthreads();
#pragma unroll
        for (int kk = 0; kk < 32; kk++) {
            float4 a0 = *(const float4*)&xT[kk][ty * 8];
            float4 a1 = *(const float4*)&xT[kk][ty * 8 + 4];
            const ulonglong2* bp = (const ulonglong2*)&ws[kk][tx * 8];
            ulonglong2 b01 = bp[0];
            ulonglong2 b23 = bp[1];
            float a[8] = {a0.x, a0.y, a0.z, a0.w, a1.x, a1.y, a1.z, a1.w};
#pragma unroll
            for (int i = 0; i < 8; i++) {
                unsigned long long aa;
                asm("mov.b64 %0, {%1, %1};" : "=l"(aa) : "f"(a[i]));
                fma2(acc2[i][0], aa, b01.x);
                fma2(acc2[i][1], aa, b01.y);
                fma2(acc2[i][2], aa, b23.x);
                fma2(acc2[i][3], aa, b23.y);
            }
        }
        __syncthreads();
    }
#pragma unroll
    for (int i = 0; i < 8; i++) {
        int gr = rowbase + ty * 8 + i;
        if (gr < NN) {
            ulonglong2* o0 = (ulonglong2*)&C[(size_t)gr * 64 + tx * 8];
            o0[0] = make_ulonglong2(acc2[i][0], acc2[i][1]);
            o0[1] = make_ulonglong2(acc2[i][2], acc2[i][3]);
        }
    }
}

// ---------------- aggregation (warp per flat node, 64-dim, MLP-8) -----------
// 8 independent row loads in flight; accumulation strictly ascending order.
__global__ void k_agg64(const float* __restrict__ biasAll,
                        const float* __restrict__ W2all, int layer) {
    int gt   = blockIdx.x * blockDim.x + threadIdx.x;
    int n    = gt >> 5;
    int lane = gt & 31;
    if (n >= NT3) return;
    int r = n / NN;
    const float* __restrict__ hl = g_hlin + (size_t)r * NN * HIDD;
    int ln = n - r * NN;
    const float* bias = biasAll + r * 64;

    int d0 = 2 * lane, d1 = 2 * lane + 1;
    float acc0 = 0.f, acc1 = 0.f;
    int e = g_off[n], e1 = g_off[n + 1];

    for (; e + 8 <= e1; e += 8) {
        float2 p0 = g_epair[e],     p1 = g_epair[e + 1];
        float2 p2 = g_epair[e + 2], p3 = g_epair[e + 3];
        float2 p4 = g_epair[e + 4], p5 = g_epair[e + 5];
        float2 p6 = g_epair[e + 6], p7 = g_epair[e + 7];
        float2 h0 = *(const float2*)&hl[(size_t)__float_as_int(p0.y) * 64 + d0];
        float2 h1 = *(const float2*)&hl[(size_t)__float_as_int(p1.y) * 64 + d0];
        float2 h2 = *(const float2*)&hl[(size_t)__float_as_int(p2.y) * 64 + d0];
        float2 h3 = *(const float2*)&hl[(size_t)__float_as_int(p3.y) * 64 + d0];
        float2 h4 = *(const float2*)&hl[(size_t)__float_as_int(p4.y) * 64 + d0];
        float2 h5 = *(const float2*)&hl[(size_t)__float_as_int(p5.y) * 64 + d0];
        float2 h6 = *(const float2*)&hl[(size_t)__float_as_int(p6.y) * 64 + d0];
        float2 h7 = *(const float2*)&hl[(size_t)__float_as_int(p7.y) * 64 + d0];
        acc0 = __fadd_rn(acc0, __fmul_rn(p0.x, h0.x)); acc1 = __fadd_rn(acc1, __fmul_rn(p0.x, h0.y));
        acc0 = __fadd_rn(acc0, __fmul_rn(p1.x, h1.x)); acc1 = __fadd_rn(acc1, __fmul_rn(p1.x, h1.y));
        acc0 = __fadd_rn(acc0, __fmul_rn(p2.x, h2.x)); acc1 = __fadd_rn(acc1, __fmul_rn(p2.x, h2.y));
        acc0 = __fadd_rn(acc0, __fmul_rn(p3.x, h3.x)); acc1 = __fadd_rn(acc1, __fmul_rn(p3.x, h3.y));
        acc0 = __fadd_rn(acc0, __fmul_rn(p4.x, h4.x)); acc1 = __fadd_rn(acc1, __fmul_rn(p4.x, h4.y));
        acc0 = __fadd_rn(acc0, __fmul_rn(p5.x, h5.x)); acc1 = __fadd_rn(acc1, __fmul_rn(p5.x, h5.y));
        acc0 = __fadd_rn(acc0, __fmul_rn(p6.x, h6.x)); acc1 = __fadd_rn(acc1, __fmul_rn(p6.x, h6.y));
        acc0 = __fadd_rn(acc0, __fmul_rn(p7.x, h7.x)); acc1 = __fadd_rn(acc1, __fmul_rn(p7.x, h7.y));
    }
    for (; e < e1; e++) {
        float2 p = g_epair[e];
        float2 h = *(const float2*)&hl[(size_t)__float_as_int(p.y) * 64 + d0];
        acc0 = __fadd_rn(acc0, __fmul_rn(p.x, h.x));
        acc1 = __fadd_rn(acc1, __fmul_rn(p.x, h.y));
    }

    float dv = g_dinv[n];
    float sn = __fmul_rn(dv, dv);
    float2 hs = *(const float2*)&hl[(size_t)ln * 64 + d0];
    acc0 = __fadd_rn(acc0, __fmul_rn(sn, hs.x));
    acc1 = __fadd_rn(acc1, __fmul_rn(sn, hs.y));
    acc0 = __fadd_rn(acc0, bias[d0]);
    acc1 = __fadd_rn(acc1, bias[d1]);
    float v0 = xla_tanh(acc0);
    float v1 = xla_tanh(acc1);

    size_t fb = (size_t)n * DF + (layer == 1 ? 0 : 64);
    g_feat[fb + d0] = v0;
    g_feat[fb + d1] = v1;
    if (layer == 1) {
        *(float2*)&g_h1[(size_t)n * 64 + d0] = make_float2(v0, v1);
    } else {
        const float* w2 = W2all + r * 64;
        double part = (double)v0 * (double)w2[d0] + (double)v1 * (double)w2[d1];
#pragma unroll
        for (int o = 16; o > 0; o >>= 1)
            part += __shfl_xor_sync(0xffffffffu, part, o);
        if (lane == 0) g_h3lin[n] = (float)part;
    }
}

// scalar aggregation for the score channel (MLP-4)
__global__ void k_agg1(const float* __restrict__ b2) {
    int n = blockIdx.x * blockDim.x + threadIdx.x;
    if (n >= NT3) return;
    int r = n / NN;
    const float* __restrict__ h3 = g_h3lin + r * NN;
    int e = g_off[n], e1 = g_off[n + 1];
    float acc = 0.f;
    for (; e + 4 <= e1; e += 4) {
        float2 p0 = g_epair[e],     p1 = g_epair[e + 1];
        float2 p2 = g_epair[e + 2], p3 = g_epair[e + 3];
        float v0 = h3[__float_as_int(p0.y)];
        float v1 = h3[__float_as_int(p1.y)];
        float v2 = h3[__float_as_int(p2.y)];
        float v3 = h3[__float_as_int(p3.y)];
        acc = __fadd_rn(acc, __fmul_rn(p0.x, v0));
        acc = __fadd_rn(acc, __fmul_rn(p1.x, v1));
        acc = __fadd_rn(acc, __fmul_rn(p2.x, v2));
        acc = __fadd_rn(acc, __fmul_rn(p3.x, v3));
    }
    for (; e < e1; e++) {
        float2 p = g_epair[e];
        acc = __fadd_rn(acc, __fmul_rn(p.x, h3[__float_as_int(p.y)]));
    }
    float dv = g_dinv[n];
    float sn = __fmul_rn(dv, dv);
    acc = __fadd_rn(acc, __fmul_rn(sn, g_h3lin[n]));
    acc = __fadd_rn(acc, b2[r]);
    g_feat[(size_t)n * DF + 128] = xla_tanh(acc);
}

// ---------------- fused gscore + topk + conv per (relation,group) -----------
struct P1 { float sc[GCAP]; int id[GCAP]; };
struct P2 {
    float sf[KK * DF];
    float sw1[NC1 * DF];
    float sy[NC1 * KK];
    float sp2[NC1 * POOLL];
    float sw2[NC2 * NC1 * KSZ];
};
union PU { P1 p1; P2 p2; };

__global__ __launch_bounds__(256) void k_topk_conv(
        const float* __restrict__ w1, const float* __restrict__ b1,
        const float* __restrict__ w2, const float* __restrict__ b2) {
    int b = blockIdx.x;                  // r*GG + g
    int r = b / GG, g = b - r * GG;
    int t = threadIdx.x;
    int base = g_goff[g];
    int cnt  = g_goff[g + 1] - base;

    __shared__ PU u;
    __shared__ float ss[256];
    __shared__ int   si[256];
    __shared__ int   sp[256];
    __shared__ int   stopk[KK];

    if (cnt <= GCAP) {
        for (int i = t; i < cnt; i += 256) {
            int id = g_gids[base + i];
            u.p1.id[i] = id;
            u.p1.sc[i] = g_feat[(size_t)(r * NN + id) * DF + 128];
        }
        __syncthreads();
        for (int it = 0; it < KK; it++) {
            float bs = NEGINF;
            int bi = 0x7fffffff, bp = -1;
            for (int i = t; i < cnt; i += 256) {
                float sc = u.p1.sc[i];
                int   id = u.p1.id[i];
                if (sc > bs || (sc == bs && id < bi)) { bs = sc; bi = id; bp = i; }
            }
            ss[t] = bs; si[t] = bi; sp[t] = bp;
            __syncthreads();
            for (int d = 128; d > 0; d >>= 1) {
                if (t < d) {
                    if (ss[t + d] > ss[t] || (ss[t + d] == ss[t] && si[t + d] < si[t])) {
                        ss[t] = ss[t + d]; si[t] = si[t + d]; sp[t] = sp[t + d];
                    }
                }
                __syncthreads();
            }
            if (t == 0) {
                stopk[it] = si[0];
                if (sp[0] >= 0) u.p1.sc[sp[0]] = NEGINF;
            }
            __syncthreads();
        }
    } else {
        for (int it = 0; it < KK; it++) {
            float bs = NEGINF;
            int bi = 0x7fffffff, bp = -1;
            for (int i = t; i < cnt; i += 256) {
                int id = g_gids[base + i];
                bool taken = false;
                for (int j = 0; j < it; j++) taken |= (stopk[j] == id);
                if (taken) continue;
                float sc = g_feat[(size_t)(r * NN + id) * DF + 128];
                if (sc > bs || (sc == bs && id < bi)) { bs = sc; bi = id; bp = i; }
            }
            ss[t] = bs; si[t] = bi; sp[t] = bp;
            __syncthreads();
            for (int d = 128; d > 0; d >>= 1) {
                if (t < d) {
                    if (ss[t + d] > ss[t] || (ss[t + d] == ss[t] && si[t + d] < si[t])) {
                        ss[t] = ss[t + d]; si[t] = si[t + d]; sp[t] = sp[t + d];
                    }
                }
                __syncthreads();
            }
            if (t == 0) stopk[it] = si[0];
            __syncthreads();
        }
    }
    __syncthreads();

    // ---- conv head (smem reused via union) ----
    for (int i = t; i < KK * DF; i += 256) {
        int row = i / DF, col = i - row * DF;
        u.p2.sf[i] = g_feat[(size_t)(r * NN + stopk[row]) * DF + col];
    }
    for (int i = t; i < NC1 * DF; i += 256) u.p2.sw1[i] = w1[i];
    for (int i = t; i < NC2 * NC1 * KSZ; i += 256) u.p2.sw2[i] = w2[i];
    __syncthreads();

    for (int o = t; o < NC1 * KK; o += 256) {
        int c = o / KK, tt = o - c * KK;
        float acc = b1[c];
#pragma unroll 4
        for (int j = 0; j < DF; j++)
            acc = fmaf(u.p2.sw1[c * DF + j], u.p2.sf[tt * DF + j], acc);
        u.p2.sy[c * KK + tt] = fmaxf(acc, 0.f);
    }
    __syncthreads();

    for (int o = t; o < NC1 * POOLL; o += 256) {
        int c = o / POOLL, p = o - c * POOLL;
        u.p2.sp2[c * POOLL + p] = fmaxf(u.p2.sy[c * KK + 2 * p], u.p2.sy[c * KK + 2 * p + 1]);
    }
    __syncthreads();

    for (int o2 = t; o2 < NC2 * TOUT; o2 += 256) {
        int o = o2 / TOUT, tt = o2 - o * TOUT;
        float acc = b2[o];
#pragma unroll
        for (int i = 0; i < NC1; i++)
#pragma unroll
            for (int k = 0; k < KSZ; k++)
                acc = fmaf(u.p2.sw2[(o * NC1 + i) * KSZ + k],
                           u.p2.sp2[i * POOLL + tt + k], acc);
        g_cout[b * OUTL + o * TOUT + tt] = fmaxf(acc, 0.f);
    }
}

// sum over relations in fixed order ((y0 + y1) + y2)
__global__ void k_sumout(float* __restrict__ out) {
    int i = blockIdx.x * blockDim.x + threadIdx.x;
    if (i < GG * OUTL)
        out[i] = __fadd_rn(__fadd_rn(g_cout[i], g_cout[GG * OUTL + i]),
                           g_cout[2 * GG * OUTL + i]);
}

// ---------------- launch ----------------
extern "C" void kernel_launch(void* const* d_in, const int* in_sizes, int n_in,
                              void* d_out, int out_size) {
    const float* x   = (const float*)d_in[0];
    const int*   ei  = (const int*)d_in[1];
    const float* ew  = (const float*)d_in[2];
    const int*   grp = (const int*)d_in[3];
    const float* W0  = (const float*)d_in[4];
    const float* b0  = (const float*)d_in[5];
    const float* W1  = (const float*)d_in[6];
    const float* b1  = (const float*)d_in[7];
    const float* W2  = (const float*)d_in[8];
    const float* b2  = (const float*)d_in[9];
    const float* c1w = (const float*)d_in[10];
    const float* c1b = (const float*)d_in[11];
    const float* c2w = (const float*)d_in[12];
    const float* c2b = (const float*)d_in[13];
    float* out = (float*)d_out;

    const int TB = 256;
    const int NB_N  = (NN + TB - 1) / TB;
    const int NB_N3 = (NT3 + TB - 1) / TB;
    const int NB_E3 = (ET3 + TB - 1) / TB;
    const int NB_W3 = (NT3 * 32 + TB - 1) / TB;
    const int SCAN_NB = (NT3 + 1023) / 1024;

    k_zero<<<NB_N3, TB>>>();
    k_gcount<<<NB_N, TB>>>(grp);
    k_gscan<<<1, GG>>>();
    k_gscatter<<<NB_N, TB>>>(grp);

    k_count<<<NB_E3, TB>>>(ei);
    k_scan1<<<SCAN_NB, 1024>>>();
    k_scan2<<<1, 512>>>(SCAN_NB);
    k_scan3<<<NB_N3, TB>>>();
    k_scatter_eid<<<NB_E3, TB>>>(ei);
    k_sortdeg<<<NB_N3, TB>>>(ew);
    k_coef<<<NB_E3, TB>>>(ei, ew);

    dim3 gemm_grid((NN + 127) / 128, RR);

    k_gemm<<<gemm_grid, 128>>>(x, W0, 128, 0);
    k_agg64<<<NB_W3, TB>>>(b0, nullptr, 1);

    k_gemm<<<gemm_grid, 128>>>(nullptr, W1, 64, 1);
    k_agg64<<<NB_W3, TB>>>(b1, W2, 2);

    k_agg1<<<NB_N3, TB>>>(b2);

    k_topk_conv<<<RR * GG, 256>>>(c1w, c1b, c2w, c2b);
    k_sumout<<<(GG * OUTL + TB - 1) / TB, TB>>>(out);
}

// round 6
// speedup vs baseline: 1.3717x; 1.0105x over previous
#include <cuda_runtime.h>

// ---------------- problem constants ----------------
#define NN 100000
#define RR 3
#define EE 1600000
#define NT3 (RR * NN)            // 300000 flat nodes
#define ET3 (RR * EE)            // 4800000 flat edges
#define HIDD 64
#define DF 129                   // HID*2+1
#define KK 30                    // sort-pool k
#define GG 64                    // groups
#define NC1 16
#define NC2 32
#define KSZ 5
#define POOLL (KK/2)             // 15
#define TOUT (POOLL - KSZ + 1)   // 11
#define OUTL (NC2*TOUT)          // 352
#define NREP 64                  // replicated group counters
#define GCAP 2048                // smem score capacity per group
#define DCAP 96                  // local-sort degree cap

#define NEGINF __int_as_float(0xff800000)

// ---------------- scratch (static device globals) ----------------
__device__ float g_dinv[NT3];
__device__ int   g_cnt[NT3];
__device__ int   g_off[NT3 + 1];
__device__ int   g_cur[NT3];
__device__ int   g_eid[ET3];
__device__ float2 g_epair[ET3];        // phase A: {ew, bitcast(eid)}; phase B: {coef, bitcast(src)}
__device__ float g_hlin[(size_t)NT3 * HIDD];
__device__ float g_h1[(size_t)NT3 * HIDD];
__device__ float g_h2[(size_t)NT3 * HIDD];
__device__ float g_h3lin[NT3];
__device__ float g_score[NT3];
__device__ int   g_gcnt2[NREP][GG];
__device__ int   g_gcur2[NREP][GG];
__device__ int   g_goff[GG + 1];
__device__ int   g_gids[NN];
__device__ float g_cout[RR * GG * OUTL];
__device__ int   g_part[512];

// ---- XLA fast-tanh (llvm_ir::EmitFastTanh): rational 7/3, clamp ±9,
// |x| < 0.0004 -> x. Separate rn mul/add (no FMA contraction).
__device__ __forceinline__ float xla_tanh(float x) {
    float ax = fabsf(x);
    float cx = fminf(fmaxf(x, -9.0f), 9.0f);
    float x2 = __fmul_rn(cx, cx);
    float p = -2.76076847742355e-16f;
    p = __fadd_rn(__fmul_rn(p, x2), 2.00018790482477e-13f);
    p = __fadd_rn(__fmul_rn(p, x2), -8.60467152213735e-11f);
    p = __fadd_rn(__fmul_rn(p, x2), 5.12229709037114e-08f);
    p = __fadd_rn(__fmul_rn(p, x2), 1.48572235717979e-05f);
    p = __fadd_rn(__fmul_rn(p, x2), 6.37261928875436e-04f);
    p = __fadd_rn(__fmul_rn(p, x2), 4.89352455891786e-03f);
    float num = __fmul_rn(cx, p);
    float q = 1.19825839466702e-06f;
    q = __fadd_rn(__fmul_rn(q, x2), 1.18534705686654e-04f);
    q = __fadd_rn(__fmul_rn(q, x2), 2.26843463243900e-03f);
    q = __fadd_rn(__fmul_rn(q, x2), 4.89352518554385e-03f);
    float r = __fdiv_rn(num, q);
    return (ax < 0.0004f) ? x : r;
}

// ---------------- zero: g_cnt + replicated group counters ----------------
__global__ void k_zero() {
    int i = blockIdx.x * blockDim.x + threadIdx.x;
    if (i < NT3) g_cnt[i] = 0;
    if (i < NREP * GG) (&g_gcnt2[0][0])[i] = 0;
}

// edge histogram (all relations) + group histogram in one kernel
__global__ void k_count2(const int* __restrict__ ei, const int* __restrict__ grp) {
    int e = blockIdx.x * blockDim.x + threadIdx.x;
    if (e < ET3) {
        int r  = e / EE;
        int le = e - r * EE;
        int d  = ei[(size_t)r * 2 * EE + EE + le];
        atomicAdd(&g_cnt[r * NN + d], 1);
    }
    if (e < NN) atomicAdd(&g_gcnt2[blockIdx.x & (NREP - 1)][grp[e]], 1);
}

__global__ void k_gscan() {  // 1 block, GG threads
    __shared__ int stot[GG];
    int g = threadIdx.x;
    int tot = 0;
    for (int rep = 0; rep < NREP; rep++) {
        int c = g_gcnt2[rep][g];
        g_gcnt2[rep][g] = tot;
        tot += c;
    }
    stot[g] = tot; __syncthreads();
    for (int d = 1; d < GG; d <<= 1) {
        int a = (g >= d) ? stot[g - d] : 0;
        __syncthreads();
        stot[g] += a;
        __syncthreads();
    }
    int excl = stot[g] - tot;
    g_goff[g] = excl;
    if (g == GG - 1) g_goff[GG] = stot[g];
    for (int rep = 0; rep < NREP; rep++)
        g_gcur2[rep][g] = excl + g_gcnt2[rep][g];
}

__global__ void k_gscatter(const int* __restrict__ grp) {
    int n = blockIdx.x * blockDim.x + threadIdx.x;
    if (n < NN) {
        int pos = atomicAdd(&g_gcur2[blockIdx.x & (NREP - 1)][grp[n]], 1);
        g_gids[pos] = n;
    }
}

// ---------------- CSR scans ----------------
__global__ void k_scan1() {
    __shared__ int s[1024];
    int t = threadIdx.x;
    int gid = blockIdx.x * 1024 + t;
    int v = (gid < NT3) ? g_cnt[gid] : 0;
    s[t] = v; __syncthreads();
    for (int d = 1; d < 1024; d <<= 1) {
        int a = (t >= d) ? s[t - d] : 0;
        __syncthreads();
        s[t] += a;
        __syncthreads();
    }
    if (gid < NT3) g_off[gid] = s[t];
    if (t == 1023) g_part[blockIdx.x] = s[t];
}

__global__ void k_scan2(int nb) {
    __shared__ int s[512];
    int t = threadIdx.x;
    int v = (t < nb) ? g_part[t] : 0;
    s[t] = v; __syncthreads();
    for (int d = 1; d < 512; d <<= 1) {
        int a = (t >= d) ? s[t - d] : 0;
        __syncthreads();
        s[t] += a;
        __syncthreads();
    }
    if (t < nb) g_part[t] = s[t];
}

__global__ void k_scan3() {
    int i = blockIdx.x * blockDim.x + threadIdx.x;
    if (i < NT3) {
        int b = i >> 10;
        int pref = (b > 0) ? g_part[b - 1] : 0;
        int excl = pref + g_off[i] - g_cnt[i];
        g_off[i] = excl;
        g_cur[i] = excl;
        if (i == 0) g_off[NT3] = ET3;
    }
}

__global__ void k_scatter_eid(const int* __restrict__ ei) {
    int e = blockIdx.x * blockDim.x + threadIdx.x;
    if (e < ET3) {
        int r  = e / EE;
        int le = e - r * EE;
        int d  = ei[(size_t)r * 2 * EE + EE + le];
        int pos = atomicAdd(&g_cur[r * NN + d], 1);
        g_eid[pos] = le;
    }
}

// per-node local-memory sort of edge ids (ascending original order); writes
// packed {ew, bitcast(eid)} to g_epair and deg/dinv in the same pass.
__global__ void k_sortdeg(const float* __restrict__ ew) {
    int n = blockIdx.x * blockDim.x + threadIdx.x;
    if (n >= NT3) return;
    int r = n / NN;
    const float* ewr = ew + (size_t)r * EE;
    int s = g_off[n], e = g_off[n + 1];
    int d = e - s;
    float deg = 0.f;
    if (d <= DCAP) {
        int loc[DCAP];
        for (int i = 0; i < d; i++) loc[i] = g_eid[s + i];
        for (int i = 1; i < d; i++) {
            int key = loc[i];
            int j = i - 1;
            while (j >= 0 && loc[j] > key) { loc[j + 1] = loc[j]; j--; }
            loc[j + 1] = key;
        }
        for (int i = 0; i < d; i++) {
            int le = loc[i];
            float w = ewr[le];
            deg = __fadd_rn(deg, w);
            g_epair[s + i] = make_float2(w, __int_as_float(le));
        }
    } else {
        for (int i = s + 1; i < e; i++) {
            int key = g_eid[i];
            int j = i - 1;
            while (j >= s && g_eid[j] > key) { g_eid[j + 1] = g_eid[j]; j--; }
            g_eid[j + 1] = key;
        }
        for (int p = s; p < e; p++) {
            int le = g_eid[p];
            float w = ewr[le];
            deg = __fadd_rn(deg, w);
            g_epair[p] = make_float2(w, __int_as_float(le));
        }
    }
    g_dinv[n] = __fdiv_rn(1.0f, __fsqrt_rn(__fadd_rn(deg, 1.0f)));
}

// node-parallel coef: dst = segment owner (no dst gather, dinv[dst] hoisted).
// epair {ew, eid} -> {coef, src}, coef = (dinv[src]*ew)*dinv[dst]. MLP-4.
__global__ void k_coef(const int* __restrict__ ei) {
    int n = blockIdx.x * blockDim.x + threadIdx.x;
    if (n >= NT3) return;
    int r = n / NN;
    const int* __restrict__ srcr = ei + (size_t)r * 2 * EE;
    const float* __restrict__ dinvr = g_dinv + r * NN;
    float dvd = g_dinv[n];
    int p = g_off[n], e1 = g_off[n + 1];
    for (; p + 4 <= e1; p += 4) {
        float2 a0 = g_epair[p],     a1 = g_epair[p + 1];
        float2 a2 = g_epair[p + 2], a3 = g_epair[p + 3];
        int s0 = srcr[__float_as_int(a0.y)];
        int s1 = srcr[__float_as_int(a1.y)];
        int s2 = srcr[__float_as_int(a2.y)];
        int s3 = srcr[__float_as_int(a3.y)];
        float c0 = __fmul_rn(__fmul_rn(dinvr[s0], a0.x), dvd);
        float c1 = __fmul_rn(__fmul_rn(dinvr[s1], a1.x), dvd);
        float c2 = __fmul_rn(__fmul_rn(dinvr[s2], a2.x), dvd);
        float c3 = __fmul_rn(__fmul_rn(dinvr[s3], a3.x), dvd);
        g_epair[p]     = make_float2(c0, __int_as_float(s0));
        g_epair[p + 1] = make_float2(c1, __int_as_float(s1));
        g_epair[p + 2] = make_float2(c2, __int_as_float(s2));
        g_epair[p + 3] = make_float2(c3, __int_as_float(s3));
    }
    for (; p < e1; p++) {
        float2 a = g_epair[p];
        int s = srcr[__float_as_int(a.y)];
        float c = __fmul_rn(__fmul_rn(dinvr[s], a.x), dvd);
        g_epair[p] = make_float2(c, __int_as_float(s));
    }
}

// ---------------- SGEMM (batched over r): [M x Kd] * [Kd x 64] -> g_hlin ----
__device__ __forceinline__ void fma2(unsigned long long& acc,
                                     unsigned long long a,
                                     unsigned long long b) {
    asm("fma.rn.f32x2 %0, %1, %2, %0;" : "+l"(acc) : "l"(a), "l"(b));
}

__global__ __launch_bounds__(128) void k_gemm(const float* __restrict__ Aext,
                                              const float* __restrict__ Ball,
                                              int Kd, int asel) {
    const int r = blockIdx.y;
    const float* __restrict__ A = (asel == 0) ? Aext : (g_h1 + (size_t)r * NN * HIDD);
    const float* __restrict__ B = Ball + (size_t)r * Kd * 64;
    float* __restrict__ C = g_hlin + (size_t)r * NN * HIDD;

    __shared__ float xT[32][132];
    __shared__ float ws[32][64];
    const int t  = threadIdx.x;
    const int tx = t & 7;
    const int ty = t >> 3;
    const int rowbase = blockIdx.x * 128;

    unsigned long long acc2[8][4];
#pragma unroll
    for (int i = 0; i < 8; i++)
#pragma unroll
        for (int j = 0; j < 4; j++) acc2[i][j] = 0ull;

    for (int k0 = 0; k0 < Kd; k0 += 32) {
        for (int i = t; i < 128 * 32; i += 128) {
            int row = i >> 5, kk = i & 31;
            int gr = rowbase + row;
            xT[kk][row] = (gr < NN) ? A[(size_t)gr * Kd + k0 + kk] : 0.f;
        }
        for (int i = t; i < 32 * 64; i += 128) {
            int kk = i >> 6, col = i & 63;
            ws[kk][col] = B[(size_t)(k0 + kk) * 64 + col];
        }
        __syncthreads();
#pragma unroll
        for (int kk = 0; kk < 32; kk++) {
            float4 a0 = *(const float4*)&xT[kk][ty * 8];
            float4 a1 = *(const float4*)&xT[kk][ty * 8 + 4];
            const ulonglong2* bp = (const ulonglong2*)&ws[kk][tx * 8];
            ulonglong2 b01 = bp[0];
            ulonglong2 b23 = bp[1];
            float a[8] = {a0.x, a0.y, a0.z, a0.w, a1.x, a1.y, a1.z, a1.w};
#pragma unroll
            for (int i = 0; i < 8; i++) {
                unsigned long long aa;
                asm("mov.b64 %0, {%1, %1};" : "=l"(aa) : "f"(a[i]));
                fma2(acc2[i][0], aa, b01.x);
                fma2(acc2[i][1], aa, b01.y);
                fma2(acc2[i][2], aa, b23.x);
                fma2(acc2[i][3], aa, b23.y);
            }
        }
        __syncthreads();
    }
#pragma unroll
    for (int i = 0; i < 8; i++) {
        int gr = rowbase + ty * 8 + i;
        if (gr < NN) {
            ulonglong2* o0 = (ulonglong2*)&C[(size_t)gr * 64 + tx * 8];
            o0[0] = make_ulonglong2(acc2[i][0], acc2[i][1]);
            o0[1] = make_ulonglong2(acc2[i][2], acc2[i][3]);
        }
    }
}

// ---------------- aggregation (warp per flat node, 64-dim, MLP-8) -----------
__global__ void k_agg64(const float* __restrict__ biasAll,
                        const float* __restrict__ W2all, int layer) {
    int gt   = blockIdx.x * blockDim.x + threadIdx.x;
    int n    = gt >> 5;
    int lane = gt & 31;
    if (n >= NT3) return;
    int r = n / NN;
    const float* __restrict__ hl = g_hlin + (size_t)r * NN * HIDD;
    int ln = n - r * NN;
    const float* bias = biasAll + r * 64;

    int d0 = 2 * lane, d1 = 2 * lane + 1;
    float acc0 = 0.f, acc1 = 0.f;
    int e = g_off[n], e1 = g_off[n + 1];

    for (; e + 8 <= e1; e += 8) {
        float2 p0 = g_epair[e],     p1 = g_epair[e + 1];
        float2 p2 = g_epair[e + 2], p3 = g_epair[e + 3];
        float2 p4 = g_epair[e + 4], p5 = g_epair[e + 5];
        float2 p6 = g_epair[e + 6], p7 = g_epair[e + 7];
        float2 h0 = *(const float2*)&hl[(size_t)__float_as_int(p0.y) * 64 + d0];
        float2 h1 = *(const float2*)&hl[(size_t)__float_as_int(p1.y) * 64 + d0];
        float2 h2 = *(const float2*)&hl[(size_t)__float_as_int(p2.y) * 64 + d0];
        float2 h3 = *(const float2*)&hl[(size_t)__float_as_int(p3.y) * 64 + d0];
        float2 h4 = *(const float2*)&hl[(size_t)__float_as_int(p4.y) * 64 + d0];
        float2 h5 = *(const float2*)&hl[(size_t)__float_as_int(p5.y) * 64 + d0];
        float2 h6 = *(const float2*)&hl[(size_t)__float_as_int(p6.y) * 64 + d0];
        float2 h7 = *(const float2*)&hl[(size_t)__float_as_int(p7.y) * 64 + d0];
        acc0 = __fadd_rn(acc0, __fmul_rn(p0.x, h0.x)); acc1 = __fadd_rn(acc1, __fmul_rn(p0.x, h0.y));
        acc0 = __fadd_rn(acc0, __fmul_rn(p1.x, h1.x)); acc1 = __fadd_rn(acc1, __fmul_rn(p1.x, h1.y));
        acc0 = __fadd_rn(acc0, __fmul_rn(p2.x, h2.x)); acc1 = __fadd_rn(acc1, __fmul_rn(p2.x, h2.y));
        acc0 = __fadd_rn(acc0, __fmul_rn(p3.x, h3.x)); acc1 = __fadd_rn(acc1, __fmul_rn(p3.x, h3.y));
        acc0 = __fadd_rn(acc0, __fmul_rn(p4.x, h4.x)); acc1 = __fadd_rn(acc1, __fmul_rn(p4.x, h4.y));
        acc0 = __fadd_rn(acc0, __fmul_rn(p5.x, h5.x)); acc1 = __fadd_rn(acc1, __fmul_rn(p5.x, h5.y));
        acc0 = __fadd_rn(acc0, __fmul_rn(p6.x, h6.x)); acc1 = __fadd_rn(acc1, __fmul_rn(p6.x, h6.y));
        acc0 = __fadd_rn(acc0, __fmul_rn(p7.x, h7.x)); acc1 = __fadd_rn(acc1, __fmul_rn(p7.x, h7.y));
    }
    for (; e < e1; e++) {
        float2 p = g_epair[e];
        float2 h = *(const float2*)&hl[(size_t)__float_as_int(p.y) * 64 + d0];
        acc0 = __fadd_rn(acc0, __fmul_rn(p.x, h.x));
        acc1 = __fadd_rn(acc1, __fmul_rn(p.x, h.y));
    }

    float dv = g_dinv[n];
    float sn = __fmul_rn(dv, dv);
    float2 hs = *(const float2*)&hl[(size_t)ln * 64 + d0];
    acc0 = __fadd_rn(acc0, __fmul_rn(sn, hs.x));
    acc1 = __fadd_rn(acc1, __fmul_rn(sn, hs.y));
    acc0 = __fadd_rn(acc0, bias[d0]);
    acc1 = __fadd_rn(acc1, bias[d1]);
    float v0 = xla_tanh(acc0);
    float v1 = xla_tanh(acc1);

    if (layer == 1) {
        *(float2*)&g_h1[(size_t)n * 64 + d0] = make_float2(v0, v1);
    } else {
        *(float2*)&g_h2[(size_t)n * 64 + d0] = make_float2(v0, v1);
        const float* w2 = W2all + r * 64;
        double part = (double)v0 * (double)w2[d0] + (double)v1 * (double)w2[d1];
#pragma unroll
        for (int o = 16; o > 0; o >>= 1)
            part += __shfl_xor_sync(0xffffffffu, part, o);
        if (lane == 0) g_h3lin[n] = (float)part;
    }
}

// scalar aggregation for the score channel (MLP-4) -> g_score
__global__ void k_agg1(const float* __restrict__ b2) {
    int n = blockIdx.x * blockDim.x + threadIdx.x;
    if (n >= NT3) return;
    int r = n / NN;
    const float* __restrict__ h3 = g_h3lin + r * NN;
    int e = g_off[n], e1 = g_off[n + 1];
    float acc = 0.f;
    for (; e + 4 <= e1; e += 4) {
        float2 p0 = g_epair[e],     p1 = g_epair[e + 1];
        float2 p2 = g_epair[e + 2], p3 = g_epair[e + 3];
        float v0 = h3[__float_as_int(p0.y)];
        float v1 = h3[__float_as_int(p1.y)];
        float v2 = h3[__float_as_int(p2.y)];
        float v3 = h3[__float_as_int(p3.y)];
        acc = __fadd_rn(acc, __fmul_rn(p0.x, v0));
        acc = __fadd_rn(acc, __fmul_rn(p1.x, v1));
        acc = __fadd_rn(acc, __fmul_rn(p2.x, v2));
        acc = __fadd_rn(acc, __fmul_rn(p3.x, v3));
    }
    for (; e < e1; e++) {
        float2 p = g_epair[e];
        acc = __fadd_rn(acc, __fmul_rn(p.x, h3[__float_as_int(p.y)]));
    }
    float dv = g_dinv[n];
    float sn = __fmul_rn(dv, dv);
    acc = __fadd_rn(acc, __fmul_rn(sn, g_h3lin[n]));
    acc = __fadd_rn(acc, b2[r]);
    g_score[n] = xla_tanh(acc);
}

// ---------------- fused topk + conv per (relation,group) --------------------
struct P1 { float sc[GCAP]; int id[GCAP]; };
struct P2 {
    float sf[KK * DF];
    float sw1[NC1 * DF];
    float sy[NC1 * KK];
    float sp2[NC1 * POOLL];
    float sw2[NC2 * NC1 * KSZ];
};
union PU { P1 p1; P2 p2; };

__global__ __launch_bounds__(256) void k_topk_conv(
        const float* __restrict__ w1, const float* __restrict__ b1,
        const float* __restrict__ w2, const float* __restrict__ b2) {
    int b = blockIdx.x;                  // r*GG + g
    int r = b / GG, g = b - r * GG;
    int t = threadIdx.x;
    int base = g_goff[g];
    int cnt  = g_goff[g + 1] - base;

    __shared__ PU u;
    __shared__ float ss[256];
    __shared__ int   si[256];
    __shared__ int   sp[256];
    __shared__ int   stopk[KK];

    if (cnt <= GCAP) {
        for (int i = t; i < cnt; i += 256) {
            int id = g_gids[base + i];
            u.p1.id[i] = id;
            u.p1.sc[i] = g_score[r * NN + id];
        }
        __syncthreads();
        for (int it = 0; it < KK; it++) {
            float bs = NEGINF;
            int bi = 0x7fffffff, bp = -1;
            for (int i = t; i < cnt; i += 256) {
                float sc = u.p1.sc[i];
                int   id = u.p1.id[i];
                if (sc > bs || (sc == bs && id < bi)) { bs = sc; bi = id; bp = i; }
            }
            ss[t] = bs; si[t] = bi; sp[t] = bp;
            __syncthreads();
            for (int d = 128; d > 0; d >>= 1) {
                if (t < d) {
                    if (ss[t + d] > ss[t] || (ss[t + d] == ss[t] && si[t + d] < si[t])) {
                        ss[t] = ss[t + d]; si[t] = si[t + d]; sp[t] = sp[t + d];
                    }
                }
                __syncthreads();
            }
            if (t == 0) {
                stopk[it] = si[0];
                if (sp[0] >= 0) u.p1.sc[sp[0]] = NEGINF;
            }
            __syncthreads();
        }
    } else {
        for (int it = 0; it < KK; it++) {
            float bs = NEGINF;
            int bi = 0x7fffffff, bp = -1;
            for (int i = t; i < cnt; i += 256) {
                int id = g_gids[base + i];
                bool taken = false;
                for (int j = 0; j < it; j++) taken |= (stopk[j] == id);
                if (taken) continue;
                float sc = g_score[r * NN + id];
                if (sc > bs || (sc == bs && id < bi)) { bs = sc; bi = id; bp = i; }
            }
            ss[t] = bs; si[t] = bi; sp[t] = bp;
            __syncthreads();
            for (int d = 128; d > 0; d >>= 1) {
                if (t < d) {
                    if (ss[t + d] > ss[t] || (ss[t + d] == ss[t] && si[t + d] < si[t])) {
                        ss[t] = ss[t + d]; si[t] = si[t + d]; sp[t] = sp[t + d];
                    }
                }
                __syncthreads();
            }
            if (t == 0) stopk[it] = si[0];
            __syncthreads();
        }
    }
    __syncthreads();

    // ---- assemble pooled rows from h1/h2/score ----
    for (int i = t; i < KK * DF; i += 256) {
        int row = i / DF, col = i - row * DF;
        size_t fn = (size_t)(r * NN + stopk[row]);
        float v;
        if (col < 64)       v = g_h1[fn * 64 + col];
        else if (col < 128) v = g_h2[fn * 64 + (col - 64)];
        else                v = g_score[fn];
        u.p2.sf[i] = v;
    }
    for (int i = t; i < NC1 * DF; i += 256) u.p2.sw1[i] = w1[i];
    for (int i = t; i < NC2 * NC1 * KSZ; i += 256) u.p2.sw2[i] = w2[i];
    __syncthreads();

    for (int o = t; o < NC1 * KK; o += 256) {
        int c = o / KK, tt = o - c * KK;
        float acc = b1[c];
#pragma unroll 4
        for (int j = 0; j < DF; j++)
            acc = fmaf(u.p2.sw1[c * DF + j], u.p2.sf[tt * DF + j], acc);
        u.p2.sy[c * KK + tt] = fmaxf(acc, 0.f);
    }
    __syncthreads();

    for (int o = t; o < NC1 * POOLL; o += 256) {
        int c = o / POOLL, p = o - c * POOLL;
        u.p2.sp2[c * POOLL + p] = fmaxf(u.p2.sy[c * KK + 2 * p], u.p2.sy[c * KK + 2 * p + 1]);
    }
    __syncthreads();

    for (int o2 = t; o2 < NC2 * TOUT; o2 += 256) {
        int o = o2 / TOUT, tt = o2 - o * TOUT;
        float acc = b2[o];
#pragma unroll
        for (int i = 0; i < NC1; i++)
#pragma unroll
            for (int k = 0; k < KSZ; k++)
                acc = fmaf(u.p2.sw2[(o * NC1 + i) * KSZ + k],
                           u.p2.sp2[i * POOLL + tt + k], acc);
        g_cout[b * OUTL + o * TOUT + tt] = fmaxf(acc, 0.f);
    }
}

// sum over relations in fixed order ((y0 + y1) + y2)
__global__ void k_sumout(float* __restrict__ out) {
    int i = blockIdx.x * blockDim.x + threadIdx.x;
    if (i < GG * OUTL)
        out[i] = __fadd_rn(__fadd_rn(g_cout[i], g_cout[GG * OUTL + i]),
                           g_cout[2 * GG * OUTL + i]);
}

// ---------------- launch ----------------
extern "C" void kernel_launch(void* const* d_in, const int* in_sizes, int n_in,
                              void* d_out, int out_size) {
    const float* x   = (const float*)d_in[0];
    const int*   ei  = (const int*)d_in[1];
    const float* ew  = (const float*)d_in[2];
    const int*   grp = (const int*)d_in[3];
    const float* W0  = (const float*)d_in[4];
    const float* b0  = (const float*)d_in[5];
    const float* W1  = (const float*)d_in[6];
    const float* b1  = (const float*)d_in[7];
    const float* W2  = (const float*)d_in[8];
    const float* b2  = (const float*)d_in[9];
    const float* c1w = (const float*)d_in[10];
    const float* c1b = (const float*)d_in[11];
    const float* c2w = (const float*)d_in[12];
    const float* c2b = (const float*)d_in[13];
    float* out = (float*)d_out;

    const int TB = 256;
    const int NB_N  = (NN + TB - 1) / TB;
    const int NB_N3 = (NT3 + TB - 1) / TB;
    const int NB_E3 = (ET3 + TB - 1) / TB;
    const int NB_W3 = (NT3 * 32 + TB - 1) / TB;
    const int SCAN_NB = (NT3 + 1023) / 1024;

    dim3 gemm_grid((NN + 127) / 128, RR);

    // launches 1-3
    k_zero<<<NB_N3, TB>>>();
    k_count2<<<NB_E3, TB>>>(ei, grp);
    k_gscan<<<1, GG>>>();
    // launch 4 == profiled slot: heavy GEMM-1 (independent of CSR build)
    k_gemm<<<gemm_grid, 128>>>(x, W0, 128, 0);

    k_gscatter<<<NB_N, TB>>>(grp);
    k_scan1<<<SCAN_NB, 1024>>>();
    k_scan2<<<1, 512>>>(SCAN_NB);
    k_scan3<<<NB_N3, TB>>>();
    k_scatter_eid<<<NB_E3, TB>>>(ei);
    k_sortdeg<<<NB_N3, TB>>>(ew);
    k_coef<<<NB_N3, TB>>>(ei);

    k_agg64<<<NB_W3, TB>>>(b0, nullptr, 1);

    k_gemm<<<gemm_grid, 128>>>(nullptr, W1, 64, 1);
    k_agg64<<<NB_W3, TB>>>(b1, W2, 2);

    k_agg1<<<NB_N3, TB>>>(b2);

    k_topk_conv<<<RR * GG, 256>>>(c1w, c1b, c2w, c2b);
    k_sumout<<<(GG * OUTL + TB - 1) / TB, TB>>>(out);
}

// round 7
// speedup vs baseline: 1.4922x; 1.0879x over previous
#include <cuda_runtime.h>

// ---------------- problem constants ----------------
#define NN 100000
#define RR 3
#define EE 1600000
#define NT3 (RR * NN)            // 300000 flat nodes
#define ET3 (RR * EE)            // 4800000 flat edges
#define HIDD 64
#define DF 129                   // HID*2+1
#define KK 30                    // sort-pool k
#define GG 64                    // groups
#define NC1 16
#define NC2 32
#define KSZ 5
#define POOLL (KK/2)             // 15
#define TOUT (POOLL - KSZ + 1)   // 11
#define OUTL (NC2*TOUT)          // 352
#define NREP 64                  // replicated group counters
#define GCAP 2048                // smem score capacity per group
#define DCAP 96                  // local-sort degree cap
#define XAS 33                   // padded A-tile row stride (floats)

#define NEGINF __int_as_float(0xff800000)

// ---------------- scratch (static device globals) ----------------
__device__ float g_dinv[NT3];
__device__ int   g_cnt[NT3];
__device__ int   g_off[NT3 + 1];
__device__ int   g_cur[NT3];
__device__ int   g_eid[ET3];
__device__ float2 g_epair[ET3];        // phase A: {ew, bitcast(eid)}; phase B: {coef, bitcast(src)}
__device__ float g_hlin[(size_t)NT3 * HIDD];
__device__ float g_h1[(size_t)NT3 * HIDD];
__device__ float g_h2[(size_t)NT3 * HIDD];
__device__ float g_h3lin[NT3];
__device__ float g_score[NT3];
__device__ int   g_gcnt2[NREP][GG];
__device__ int   g_gcur2[NREP][GG];
__device__ int   g_goff[GG + 1];
__device__ int   g_gids[NN];
__device__ float g_cout[RR * GG * OUTL];
__device__ int   g_part[512];

// ---- XLA fast-tanh (llvm_ir::EmitFastTanh): rational 7/3, clamp ±9,
// |x| < 0.0004 -> x. Separate rn mul/add (no FMA contraction).
__device__ __forceinline__ float xla_tanh(float x) {
    float ax = fabsf(x);
    float cx = fminf(fmaxf(x, -9.0f), 9.0f);
    float x2 = __fmul_rn(cx, cx);
    float p = -2.76076847742355e-16f;
    p = __fadd_rn(__fmul_rn(p, x2), 2.00018790482477e-13f);
    p = __fadd_rn(__fmul_rn(p, x2), -8.60467152213735e-11f);
    p = __fadd_rn(__fmul_rn(p, x2), 5.12229709037114e-08f);
    p = __fadd_rn(__fmul_rn(p, x2), 1.48572235717979e-05f);
    p = __fadd_rn(__fmul_rn(p, x2), 6.37261928875436e-04f);
    p = __fadd_rn(__fmul_rn(p, x2), 4.89352455891786e-03f);
    float num = __fmul_rn(cx, p);
    float q = 1.19825839466702e-06f;
    q = __fadd_rn(__fmul_rn(q, x2), 1.18534705686654e-04f);
    q = __fadd_rn(__fmul_rn(q, x2), 2.26843463243900e-03f);
    q = __fadd_rn(__fmul_rn(q, x2), 4.89352518554385e-03f);
    float r = __fdiv_rn(num, q);
    return (ax < 0.0004f) ? x : r;
}

// ---------------- zero: g_cnt + replicated group counters ----------------
__global__ void k_zero() {
    int i = blockIdx.x * blockDim.x + threadIdx.x;
    if (i < NT3) g_cnt[i] = 0;
    if (i < NREP * GG) (&g_gcnt2[0][0])[i] = 0;
}

// edge histogram (all relations) + group histogram in one kernel
__global__ void k_count2(const int* __restrict__ ei, const int* __restrict__ grp) {
    int e = blockIdx.x * blockDim.x + threadIdx.x;
    if (e < ET3) {
        int r  = e / EE;
        int le = e - r * EE;
        int d  = ei[(size_t)r * 2 * EE + EE + le];
        atomicAdd(&g_cnt[r * NN + d], 1);
    }
    if (e < NN) atomicAdd(&g_gcnt2[blockIdx.x & (NREP - 1)][grp[e]], 1);
}

__global__ void k_gscan() {  // 1 block, GG threads
    __shared__ int stot[GG];
    int g = threadIdx.x;
    int tot = 0;
    for (int rep = 0; rep < NREP; rep++) {
        int c = g_gcnt2[rep][g];
        g_gcnt2[rep][g] = tot;
        tot += c;
    }
    stot[g] = tot; __syncthreads();
    for (int d = 1; d < GG; d <<= 1) {
        int a = (g >= d) ? stot[g - d] : 0;
        __syncthreads();
        stot[g] += a;
        __syncthreads();
    }
    int excl = stot[g] - tot;
    g_goff[g] = excl;
    if (g == GG - 1) g_goff[GG] = stot[g];
    for (int rep = 0; rep < NREP; rep++)
        g_gcur2[rep][g] = excl + g_gcnt2[rep][g];
}

__global__ void k_gscatter(const int* __restrict__ grp) {
    int n = blockIdx.x * blockDim.x + threadIdx.x;
    if (n < NN) {
        int pos = atomicAdd(&g_gcur2[blockIdx.x & (NREP - 1)][grp[n]], 1);
        g_gids[pos] = n;
    }
}

// ---------------- CSR scans ----------------
__global__ void k_scan1() {
    __shared__ int s[1024];
    int t = threadIdx.x;
    int gid = blockIdx.x * 1024 + t;
    int v = (gid < NT3) ? g_cnt[gid] : 0;
    s[t] = v; __syncthreads();
    for (int d = 1; d < 1024; d <<= 1) {
        int a = (t >= d) ? s[t - d] : 0;
        __syncthreads();
        s[t] += a;
        __syncthreads();
    }
    if (gid < NT3) g_off[gid] = s[t];
    if (t == 1023) g_part[blockIdx.x] = s[t];
}

__global__ void k_scan2(int nb) {
    __shared__ int s[512];
    int t = threadIdx.x;
    int v = (t < nb) ? g_part[t] : 0;
    s[t] = v; __syncthreads();
    for (int d = 1; d < 512; d <<= 1) {
        int a = (t >= d) ? s[t - d] : 0;
        __syncthreads();
        s[t] += a;
        __syncthreads();
    }
    if (t < nb) g_part[t] = s[t];
}

__global__ void k_scan3() {
    int i = blockIdx.x * blockDim.x + threadIdx.x;
    if (i < NT3) {
        int b = i >> 10;
        int pref = (b > 0) ? g_part[b - 1] : 0;
        int excl = pref + g_off[i] - g_cnt[i];
        g_off[i] = excl;
        g_cur[i] = excl;
        if (i == 0) g_off[NT3] = ET3;
    }
}

__global__ void k_scatter_eid(const int* __restrict__ ei) {
    int e = blockIdx.x * blockDim.x + threadIdx.x;
    if (e < ET3) {
        int r  = e / EE;
        int le = e - r * EE;
        int d  = ei[(size_t)r * 2 * EE + EE + le];
        int pos = atomicAdd(&g_cur[r * NN + d], 1);
        g_eid[pos] = le;
    }
}

// per-node local-memory sort of edge ids (ascending original order); writes
// packed {ew, bitcast(eid)} to g_epair and deg/dinv in the same pass.
__global__ void k_sortdeg(const float* __restrict__ ew) {
    int n = blockIdx.x * blockDim.x + threadIdx.x;
    if (n >= NT3) return;
    int r = n / NN;
    const float* ewr = ew + (size_t)r * EE;
    int s = g_off[n], e = g_off[n + 1];
    int d = e - s;
    float deg = 0.f;
    if (d <= DCAP) {
        int loc[DCAP];
        for (int i = 0; i < d; i++) loc[i] = g_eid[s + i];
        for (int i = 1; i < d; i++) {
            int key = loc[i];
            int j = i - 1;
            while (j >= 0 && loc[j] > key) { loc[j + 1] = loc[j]; j--; }
            loc[j + 1] = key;
        }
        for (int i = 0; i < d; i++) {
            int le = loc[i];
            float w = ewr[le];
            deg = __fadd_rn(deg, w);
            g_epair[s + i] = make_float2(w, __int_as_float(le));
        }
    } else {
        for (int i = s + 1; i < e; i++) {
            int key = g_eid[i];
            int j = i - 1;
            while (j >= s && g_eid[j] > key) { g_eid[j + 1] = g_eid[j]; j--; }
            g_eid[j + 1] = key;
        }
        for (int p = s; p < e; p++) {
            int le = g_eid[p];
            float w = ewr[le];
            deg = __fadd_rn(deg, w);
            g_epair[p] = make_float2(w, __int_as_float(le));
        }
    }
    g_dinv[n] = __fdiv_rn(1.0f, __fsqrt_rn(__fadd_rn(deg, 1.0f)));
}

// node-parallel coef: dst = segment owner (no dst gather, dinv[dst] hoisted).
// epair {ew, eid} -> {coef, src}, coef = (dinv[src]*ew)*dinv[dst]. MLP-4.
__global__ void k_coef(const int* __restrict__ ei) {
    int n = blockIdx.x * blockDim.x + threadIdx.x;
    if (n >= NT3) return;
    int r = n / NN;
    const int* __restrict__ srcr = ei + (size_t)r * 2 * EE;
    const float* __restrict__ dinvr = g_dinv + r * NN;
    float dvd = g_dinv[n];
    int p = g_off[n], e1 = g_off[n + 1];
    for (; p + 4 <= e1; p += 4) {
        float2 a0 = g_epair[p],     a1 = g_epair[p + 1];
        float2 a2 = g_epair[p + 2], a3 = g_epair[p + 3];
        int s0 = srcr[__float_as_int(a0.y)];
        int s1 = srcr[__float_as_int(a1.y)];
        int s2 = srcr[__float_as_int(a2.y)];
        int s3 = srcr[__float_as_int(a3.y)];
        float c0 = __fmul_rn(__fmul_rn(dinvr[s0], a0.x), dvd);
        float c1 = __fmul_rn(__fmul_rn(dinvr[s1], a1.x), dvd);
        float c2 = __fmul_rn(__fmul_rn(dinvr[s2], a2.x), dvd);
        float c3 = __fmul_rn(__fmul_rn(dinvr[s3], a3.x), dvd);
        g_epair[p]     = make_float2(c0, __int_as_float(s0));
        g_epair[p + 1] = make_float2(c1, __int_as_float(s1));
        g_epair[p + 2] = make_float2(c2, __int_as_float(s2));
        g_epair[p + 3] = make_float2(c3, __int_as_float(s3));
    }
    for (; p < e1; p++) {
        float2 a = g_epair[p];
        int s = srcr[__float_as_int(a.y)];
        float c = __fmul_rn(__fmul_rn(dinvr[s], a.x), dvd);
        g_epair[p] = make_float2(c, __int_as_float(s));
    }
}

// ---------------- SGEMM v2: cp.async double-buffered --------------------
// [M x Kd] * [Kd x 64] -> g_hlin, 128x64 tile, 128 threads, 8x8 blocking,
// packed fma.rn.f32x2. Per-output accumulation: single ascending-k chain
// (bitwise identical to scalar FFMA loop).
__device__ __forceinline__ void fma2(unsigned long long& acc,
                                     unsigned long long a,
                                     unsigned long long b) {
    asm("fma.rn.f32x2 %0, %1, %2, %0;" : "+l"(acc) : "l"(a), "l"(b));
}
__device__ __forceinline__ void cp_async4(unsigned dst, const void* src, int srcsz) {
    asm volatile("cp.async.ca.shared.global [%0], [%1], 4, %2;"
                 :: "r"(dst), "l"(src), "r"(srcsz));
}
__device__ __forceinline__ void cp_async16(unsigned dst, const void* src) {
    asm volatile("cp.async.ca.shared.global [%0], [%1], 16;"
                 :: "r"(dst), "l"(src));
}

__global__ __launch_bounds__(128) void k_gemm(const float* __restrict__ Aext,
                                              const float* __restrict__ Ball,
                                              int Kd, int asel) {
    const int r = blockIdx.y;
    const float* __restrict__ A = (asel == 0) ? Aext : (g_h1 + (size_t)r * NN * HIDD);
    const float* __restrict__ B = Ball + (size_t)r * Kd * 64;
    float* __restrict__ C = g_hlin + (size_t)r * NN * HIDD;

    __shared__ float xA[2][128 * XAS];
    __shared__ float ws[2][32 * 64];
    const int t  = threadIdx.x;
    const int tx = t & 7;
    const int ty = t >> 3;
    const int rowbase = blockIdx.x * 128;
    const int nt = Kd >> 5;

    unsigned xa_s[2], ws_s[2];
    xa_s[0] = (unsigned)__cvta_generic_to_shared(&xA[0][0]);
    xa_s[1] = (unsigned)__cvta_generic_to_shared(&xA[1][0]);
    ws_s[0] = (unsigned)__cvta_generic_to_shared(&ws[0][0]);
    ws_s[1] = (unsigned)__cvta_generic_to_shared(&ws[1][0]);

    const int lrow = t >> 5;       // 0..3 (warp id)
    const int lkk  = t & 31;

    unsigned long long acc2[8][4];
#pragma unroll
    for (int i = 0; i < 8; i++)
#pragma unroll
        for (int j = 0; j < 4; j++) acc2[i][j] = 0ull;

    // tile loaders (cp.async): A rows coalesced (one row per warp-iter)
    #define LOAD_A(buf, k0)                                                      \
        _Pragma("unroll")                                                        \
        for (int i = 0; i < 32; i++) {                                           \
            int row = lrow + (i << 2);                                           \
            int gr = rowbase + row;                                              \
            cp_async4(xa_s[buf] + (unsigned)(row * XAS + lkk) * 4u,              \
                      A + (size_t)gr * Kd + (k0) + lkk, gr < NN ? 4 : 0);        \
        }
    #define LOAD_W(buf, k0)                                                      \
        _Pragma("unroll")                                                        \
        for (int i = 0; i < 4; i++) {                                            \
            int idx = t + (i << 7);                                              \
            int wrow = idx >> 4, c4 = (idx & 15) << 2;                           \
            cp_async16(ws_s[buf] + (unsigned)(wrow * 64 + c4) * 4u,              \
                       B + (size_t)((k0) + wrow) * 64 + c4);                     \
        }

    LOAD_A(0, 0); LOAD_W(0, 0);
    asm volatile("cp.async.commit_group;");

    for (int kt = 0; kt < nt; kt++) {
        int cur = kt & 1;
        if (kt + 1 < nt) {
            int k0n = (kt + 1) << 5;
            LOAD_A(cur ^ 1, k0n); LOAD_W(cur ^ 1, k0n);
            asm volatile("cp.async.commit_group;");
            asm volatile("cp.async.wait_group 1;");
        } else {
            asm volatile("cp.async.wait_group 0;");
        }
        __syncthreads();
        const float* xa = &xA[cur][ty * 8 * XAS];
        const float* wb = &ws[cur][tx * 8];
#pragma unroll
        for (int kk = 0; kk < 32; kk++) {
            ulonglong2 b01 = *(const ulonglong2*)(wb + kk * 64);
            ulonglong2 b23 = *(const ulonglong2*)(wb + kk * 64 + 4);
#pragma unroll
            for (int i = 0; i < 8; i++) {
                float av = xa[i * XAS + kk];
                unsigned long long aa;
                asm("mov.b64 %0, {%1, %1};" : "=l"(aa) : "f"(av));
                fma2(acc2[i][0], aa, b01.x);
                fma2(acc2[i][1], aa, b01.y);
                fma2(acc2[i][2], aa, b23.x);
                fma2(acc2[i][3], aa, b23.y);
            }
        }
        __syncthreads();
    }
    #undef LOAD_A
    #undef LOAD_W

#pragma unroll
    for (int i = 0; i < 8; i++) {
        int gr = rowbase + ty * 8 + i;
        if (gr < NN) {
            ulonglong2* o0 = (ulonglong2*)&C[(size_t)gr * 64 + tx * 8];
            o0[0] = make_ulonglong2(acc2[i][0], acc2[i][1]);
            o0[1] = make_ulonglong2(acc2[i][2], acc2[i][3]);
        }
    }
}

// ---------------- aggregation (warp per flat node, 64-dim, MLP-8) -----------
__global__ void k_agg64(const float* __restrict__ biasAll,
                        const float* __restrict__ W2all, int layer) {
    int gt   = blockIdx.x * blockDim.x + threadIdx.x;
    int n    = gt >> 5;
    int lane = gt & 31;
    if (n >= NT3) return;
    int r = n / NN;
    const float* __restrict__ hl = g_hlin + (size_t)r * NN * HIDD;
    int ln = n - r * NN;
    const float* bias = biasAll + r * 64;

    int d0 = 2 * lane, d1 = 2 * lane + 1;
    float acc0 = 0.f, acc1 = 0.f;
    int e = g_off[n], e1 = g_off[n + 1];

    for (; e + 8 <= e1; e += 8) {
        float2 p0 = g_epair[e],     p1 = g_epair[e + 1];
        float2 p2 = g_epair[e + 2], p3 = g_epair[e + 3];
        float2 p4 = g_epair[e + 4], p5 = g_epair[e + 5];
        float2 p6 = g_epair[e + 6], p7 = g_epair[e + 7];
        float2 h0 = *(const float2*)&hl[(size_t)__float_as_int(p0.y) * 64 + d0];
        float2 h1 = *(const float2*)&hl[(size_t)__float_as_int(p1.y) * 64 + d0];
        float2 h2 = *(const float2*)&hl[(size_t)__float_as_int(p2.y) * 64 + d0];
        float2 h3 = *(const float2*)&hl[(size_t)__float_as_int(p3.y) * 64 + d0];
        float2 h4 = *(const float2*)&hl[(size_t)__float_as_int(p4.y) * 64 + d0];
        float2 h5 = *(const float2*)&hl[(size_t)__float_as_int(p5.y) * 64 + d0];
        float2 h6 = *(const float2*)&hl[(size_t)__float_as_int(p6.y) * 64 + d0];
        float2 h7 = *(const float2*)&hl[(size_t)__float_as_int(p7.y) * 64 + d0];
        acc0 = __fadd_rn(acc0, __fmul_rn(p0.x, h0.x)); acc1 = __fadd_rn(acc1, __fmul_rn(p0.x, h0.y));
        acc0 = __fadd_rn(acc0, __fmul_rn(p1.x, h1.x)); acc1 = __fadd_rn(acc1, __fmul_rn(p1.x, h1.y));
        acc0 = __fadd_rn(acc0, __fmul_rn(p2.x, h2.x)); acc1 = __fadd_rn(acc1, __fmul_rn(p2.x, h2.y));
        acc0 = __fadd_rn(acc0, __fmul_rn(p3.x, h3.x)); acc1 = __fadd_rn(acc1, __fmul_rn(p3.x, h3.y));
        acc0 = __fadd_rn(acc0, __fmul_rn(p4.x, h4.x)); acc1 = __fadd_rn(acc1, __fmul_rn(p4.x, h4.y));
        acc0 = __fadd_rn(acc0, __fmul_rn(p5.x, h5.x)); acc1 = __fadd_rn(acc1, __fmul_rn(p5.x, h5.y));
        acc0 = __fadd_rn(acc0, __fmul_rn(p6.x, h6.x)); acc1 = __fadd_rn(acc1, __fmul_rn(p6.x, h6.y));
        acc0 = __fadd_rn(acc0, __fmul_rn(p7.x, h7.x)); acc1 = __fadd_rn(acc1, __fmul_rn(p7.x, h7.y));
    }
    for (; e < e1; e++) {
        float2 p = g_epair[e];
        float2 h = *(const float2*)&hl[(size_t)__float_as_int(p.y) * 64 + d0];
        acc0 = __fadd_rn(acc0, __fmul_rn(p.x, h.x));
        acc1 = __fadd_rn(acc1, __fmul_rn(p.x, h.y));
    }

    float dv = g_dinv[n];
    float sn = __fmul_rn(dv, dv);
    float2 hs = *(const float2*)&hl[(size_t)ln * 64 + d0];
    acc0 = __fadd_rn(acc0, __fmul_rn(sn, hs.x));
    acc1 = __fadd_rn(acc1, __fmul_rn(sn, hs.y));
    acc0 = __fadd_rn(acc0, bias[d0]);
    acc1 = __fadd_rn(acc1, bias[d1]);
    float v0 = xla_tanh(acc0);
    float v1 = xla_tanh(acc1);

    if (layer == 1) {
        *(float2*)&g_h1[(size_t)n * 64 + d0] = make_float2(v0, v1);
    } else {
        *(float2*)&g_h2[(size_t)n * 64 + d0] = make_float2(v0, v1);
        const float* w2 = W2all + r * 64;
        double part = (double)v0 * (double)w2[d0] + (double)v1 * (double)w2[d1];
#pragma unroll
        for (int o = 16; o > 0; o >>= 1)
            part += __shfl_xor_sync(0xffffffffu, part, o);
        if (lane == 0) g_h3lin[n] = (float)part;
    }
}

// scalar aggregation for the score channel (MLP-4) -> g_score
__global__ void k_agg1(const float* __restrict__ b2) {
    int n = blockIdx.x * blockDim.x + threadIdx.x;
    if (n >= NT3) return;
    int r = n / NN;
    const float* __restrict__ h3 = g_h3lin + r * NN;
    int e = g_off[n], e1 = g_off[n + 1];
    float acc = 0.f;
    for (; e + 4 <= e1; e += 4) {
        float2 p0 = g_epair[e],     p1 = g_epair[e + 1];
        float2 p2 = g_epair[e + 2], p3 = g_epair[e + 3];
        float v0 = h3[__float_as_int(p0.y)];
        float v1 = h3[__float_as_int(p1.y)];
        float v2 = h3[__float_as_int(p2.y)];
        float v3 = h3[__float_as_int(p3.y)];
        acc = __fadd_rn(acc, __fmul_rn(p0.x, v0));
        acc = __fadd_rn(acc, __fmul_rn(p1.x, v1));
        acc = __fadd_rn(acc, __fmul_rn(p2.x, v2));
        acc = __fadd_rn(acc, __fmul_rn(p3.x, v3));
    }
    for (; e < e1; e++) {
        float2 p = g_epair[e];
        acc = __fadd_rn(acc, __fmul_rn(p.x, h3[__float_as_int(p.y)]));
    }
    float dv = g_dinv[n];
    float sn = __fmul_rn(dv, dv);
    acc = __fadd_rn(acc, __fmul_rn(sn, g_h3lin[n]));
    acc = __fadd_rn(acc, b2[r]);
    g_score[n] = xla_tanh(acc);
}

// ---------------- fused topk + conv per (relation,group) --------------------
struct P1 { float sc[GCAP]; int id[GCAP]; };
struct P2 {
    float sf[KK * DF];
    float sw1[NC1 * DF];
    float sy[NC1 * KK];
    float sp2[NC1 * POOLL];
    float sw2[NC2 * NC1 * KSZ];
};
union PU { P1 p1; P2 p2; };

__global__ __launch_bounds__(256) void k_topk_conv(
        const float* __restrict__ w1, const float* __restrict__ b1,
        const float* __restrict__ w2, const float* __restrict__ b2) {
    int b = blockIdx.x;                  // r*GG + g
    int r = b / GG, g = b - r * GG;
    int t = threadIdx.x;
    int base = g_goff[g];
    int cnt  = g_goff[g + 1] - base;

    __shared__ PU u;
    __shared__ float ss[256];
    __shared__ int   si[256];
    __shared__ int   sp[256];
    __shared__ int   stopk[KK];

    if (cnt <= GCAP) {
        for (int i = t; i < cnt; i += 256) {
            int id = g_gids[base + i];
            u.p1.id[i] = id;
            u.p1.sc[i] = g_score[r * NN + id];
        }
        __syncthreads();
        for (int it = 0; it < KK; it++) {
            float bs = NEGINF;
            int bi = 0x7fffffff, bp = -1;
            for (int i = t; i < cnt; i += 256) {
                float sc = u.p1.sc[i];
                int   id = u.p1.id[i];
                if (sc > bs || (sc == bs && id < bi)) { bs = sc; bi = id; bp = i; }
            }
            ss[t] = bs; si[t] = bi; sp[t] = bp;
            __syncthreads();
            for (int d = 128; d > 0; d >>= 1) {
                if (t < d) {
                    if (ss[t + d] > ss[t] || (ss[t + d] == ss[t] && si[t + d] < si[t])) {
                        ss[t] = ss[t + d]; si[t] = si[t + d]; sp[t] = sp[t + d];
                    }
                }
                __syncthreads();
            }
            if (t == 0) {
                stopk[it] = si[0];
                if (sp[0] >= 0) u.p1.sc[sp[0]] = NEGINF;
            }
            __syncthreads();
        }
    } else {
        for (int it = 0; it < KK; it++) {
            float bs = NEGINF;
            int bi = 0x7fffffff, bp = -1;
            for (int i = t; i < cnt; i += 256) {
                int id = g_gids[base + i];
                bool taken = false;
                for (int j = 0; j < it; j++) taken |= (stopk[j] == id);
                if (taken) continue;
                float sc = g_score[r * NN + id];
                if (sc > bs || (sc == bs && id < bi)) { bs = sc; bi = id; bp = i; }
            }
            ss[t] = bs; si[t] = bi; sp[t] = bp;
            __syncthreads();
            for (int d = 128; d > 0; d >>= 1) {
                if (t < d) {
                    if (ss[t + d] > ss[t] || (ss[t + d] == ss[t] && si[t + d] < si[t])) {
                        ss[t] = ss[t + d]; si[t] = si[t + d]; sp[t] = sp[t + d];
                    }
                }
                __syncthreads();
            }
            if (t == 0) stopk[it] = si[0];
            __syncthreads();
        }
    }
    __syncthreads();

    // ---- assemble pooled rows from h1/h2/score ----
    for (int i = t; i < KK * DF; i += 256) {
        int row = i / DF, col = i - row * DF;
        size_t fn = (size_t)(r * NN + stopk[row]);
        float v;
        if (col < 64)       v = g_h1[fn * 64 + col];
        else if (col < 128) v = g_h2[fn * 64 + (col - 64)];
        else                v = g_score[fn];
        u.p2.sf[i] = v;
    }
    for (int i = t; i < NC1 * DF; i += 256) u.p2.sw1[i] = w1[i];
    for (int i = t; i < NC2 * NC1 * KSZ; i += 256) u.p2.sw2[i] = w2[i];
    __syncthreads();

    for (int o = t; o < NC1 * KK; o += 256) {
        int c = o / KK, tt = o - c * KK;
        float acc = b1[c];
#pragma unroll 4
        for (int j = 0; j < DF; j++)
            acc = fmaf(u.p2.sw1[c * DF + j], u.p2.sf[tt * DF + j], acc);
        u.p2.sy[c * KK + tt] = fmaxf(acc, 0.f);
    }
    __syncthreads();

    for (int o = t; o < NC1 * POOLL; o += 256) {
        int c = o / POOLL, p = o - c * POOLL;
        u.p2.sp2[c * POOLL + p] = fmaxf(u.p2.sy[c * KK + 2 * p], u.p2.sy[c * KK + 2 * p + 1]);
    }
    __syncthreads();

    for (int o2 = t; o2 < NC2 * TOUT; o2 += 256) {
        int o = o2 / TOUT, tt = o2 - o * TOUT;
        float acc = b2[o];
#pragma unroll
        for (int i = 0; i < NC1; i++)
#pragma unroll
            for (int k = 0; k < KSZ; k++)
                acc = fmaf(u.p2.sw2[(o * NC1 + i) * KSZ + k],
                           u.p2.sp2[i * POOLL + tt + k], acc);
        g_cout[b * OUTL + o * TOUT + tt] = fmaxf(acc, 0.f);
    }
}

// sum over relations in fixed order ((y0 + y1) + y2)
__global__ void k_sumout(float* __restrict__ out) {
    int i = blockIdx.x * blockDim.x + threadIdx.x;
    if (i < GG * OUTL)
        out[i] = __fadd_rn(__fadd_rn(g_cout[i], g_cout[GG * OUTL + i]),
                           g_cout[2 * GG * OUTL + i]);
}

// ---------------- launch ----------------
extern "C" void kernel_launch(void* const* d_in, const int* in_sizes, int n_in,
                              void* d_out, int out_size) {
    const float* x   = (const float*)d_in[0];
    const int*   ei  = (const int*)d_in[1];
    const float* ew  = (const float*)d_in[2];
    const int*   grp = (const int*)d_in[3];
    const float* W0  = (const float*)d_in[4];
    const float* b0  = (const float*)d_in[5];
    const float* W1  = (const float*)d_in[6];
    const float* b1  = (const float*)d_in[7];
    const float* W2  = (const float*)d_in[8];
    const float* b2  = (const float*)d_in[9];
    const float* c1w = (const float*)d_in[10];
    const float* c1b = (const float*)d_in[11];
    const float* c2w = (const float*)d_in[12];
    const float* c2b = (const float*)d_in[13];
    float* out = (float*)d_out;

    const int TB = 256;
    const int NB_N  = (NN + TB - 1) / TB;
    const int NB_N3 = (NT3 + TB - 1) / TB;
    const int NB_E3 = (ET3 + TB - 1) / TB;
    const int NB_W3 = (NT3 * 32 + TB - 1) / TB;
    const int SCAN_NB = (NT3 + 1023) / 1024;

    dim3 gemm_grid((NN + 127) / 128, RR);

    // launches 1-3
    k_zero<<<NB_N3, TB>>>();
    k_count2<<<NB_E3, TB>>>(ei, grp);
    k_gscan<<<1, GG>>>();
    // launch 4 == profiled slot: heavy GEMM-1 (independent of CSR build)
    k_gemm<<<gemm_grid, 128>>>(x, W0, 128, 0);

    k_gscatter<<<NB_N, TB>>>(grp);
    k_scan1<<<SCAN_NB, 1024>>>();
    k_scan2<<<1, 512>>>(SCAN_NB);
    k_scan3<<<NB_N3, TB>>>();
    k_scatter_eid<<<NB_E3, TB>>>(ei);
    k_sortdeg<<<NB_N3, TB>>>(ew);
    k_coef<<<NB_N3, TB>>>(ei);

    k_agg64<<<NB_W3, TB>>>(b0, nullptr, 1);

    k_gemm<<<gemm_grid, 128>>>(nullptr, W1, 64, 1);
    k_agg64<<<NB_W3, TB>>>(b1, W2, 2);

    k_agg1<<<NB_N3, TB>>>(b2);

    k_topk_conv<<<RR * GG, 256>>>(c1w, c1b, c2w, c2b);
    k_sumout<<<(GG * OUTL + TB - 1) / TB, TB>>>(out);
}